// round 1
// baseline (speedup 1.0000x reference)
#include <cuda_runtime.h>
#include <math.h>

// Problem constants
#define NUM_HEADS 16
#define HEAD_SIZE 128
#define HIDDEN    2048   // NUM_HEADS*HEAD_SIZE
#define ROT       16
#define BATCH     4
#define SEQ       1024
#define TOTAL     4096   // BATCH*SEQ
#define QKV_N     6144   // 3*HIDDEN

// -------- device scratch (static; no allocation allowed) --------
__device__ float g_qkv[(size_t)TOTAL * QKV_N];            // [T, 3*H*D] post-GEMM+bias
__device__ float g_q[(size_t)TOTAL * HIDDEN];             // [B,H,S,D]
__device__ float g_k[(size_t)TOTAL * HIDDEN];             // [B,H,S,D]
__device__ float g_v[(size_t)TOTAL * HIDDEN];             // [B,H,S,D]
__device__ float g_attn[(size_t)TOTAL * HIDDEN];          // [T, H*D]

// ============================================================================
// Kernel 1/4: classic 128x128x8 SGEMM with bias epilogue.
// C[M,N] = A[M,K] @ B[K,N] + bias[N]; A,B,C row-major. M%128==0, N%128==0, K%8==0.
// ============================================================================
__global__ void __launch_bounds__(256) sgemm_bias(
    const float* __restrict__ A, const float* __restrict__ B,
    const float* __restrict__ bias, float* __restrict__ C,
    int M, int N, int K)
{
    __shared__ float As[8][128];
    __shared__ float Bs[8][128];

    const int tid = threadIdx.x;
    const int bx = blockIdx.x;   // N tile
    const int by = blockIdx.y;   // M tile
    const int tx = tid & 15;     // 16 cols of microtiles
    const int ty = tid >> 4;     // 16 rows of microtiles

    const int aRow = tid >> 1;           // 0..127
    const int aCol = (tid & 1) << 2;     // 0 or 4
    const int bRow = tid >> 5;           // 0..7
    const int bCol = (tid & 31) << 2;    // 0..124

    const float* Ap = A + (size_t)(by * 128 + aRow) * K + aCol;
    const float* Bp = B + (size_t)bRow * N + bx * 128 + bCol;

    float acc[8][8];
#pragma unroll
    for (int i = 0; i < 8; ++i)
#pragma unroll
        for (int j = 0; j < 8; ++j) acc[i][j] = 0.0f;

    for (int k0 = 0; k0 < K; k0 += 8) {
        float4 a4 = *(const float4*)(Ap + k0);
        As[aCol + 0][aRow] = a4.x;
        As[aCol + 1][aRow] = a4.y;
        As[aCol + 2][aRow] = a4.z;
        As[aCol + 3][aRow] = a4.w;
        float4 b4 = *(const float4*)(Bp + (size_t)k0 * N);
        *(float4*)&Bs[bRow][bCol] = b4;
        __syncthreads();

#pragma unroll
        for (int kk = 0; kk < 8; ++kk) {
            float ar[8], br[8];
            *(float4*)(ar)     = *(const float4*)&As[kk][ty * 8];
            *(float4*)(ar + 4) = *(const float4*)&As[kk][ty * 8 + 4];
            *(float4*)(br)     = *(const float4*)&Bs[kk][tx * 8];
            *(float4*)(br + 4) = *(const float4*)&Bs[kk][tx * 8 + 4];
#pragma unroll
            for (int i = 0; i < 8; ++i)
#pragma unroll
                for (int j = 0; j < 8; ++j)
                    acc[i][j] = fmaf(ar[i], br[j], acc[i][j]);
        }
        __syncthreads();
    }

    const int row0 = by * 128 + ty * 8;
    const int col0 = bx * 128 + tx * 8;
    float bsv[8];
    *(float4*)(bsv)     = *(const float4*)&bias[col0];
    *(float4*)(bsv + 4) = *(const float4*)&bias[col0 + 4];
#pragma unroll
    for (int i = 0; i < 8; ++i) {
        float4 o0, o1;
        o0.x = acc[i][0] + bsv[0]; o0.y = acc[i][1] + bsv[1];
        o0.z = acc[i][2] + bsv[2]; o0.w = acc[i][3] + bsv[3];
        o1.x = acc[i][4] + bsv[4]; o1.y = acc[i][5] + bsv[5];
        o1.z = acc[i][6] + bsv[6]; o1.w = acc[i][7] + bsv[7];
        *(float4*)&C[(size_t)(row0 + i) * N + col0]     = o0;
        *(float4*)&C[(size_t)(row0 + i) * N + col0 + 4] = o1;
    }
}

// ============================================================================
// Kernel 2/4: rotary embedding (first 2*ROT dims) + split into Q/K/V [B,H,S,D]
// ============================================================================
__global__ void __launch_bounds__(256) rope_split(
    const float* __restrict__ cosb, const float* __restrict__ sinb)
{
    const int t = blockIdx.x;          // token 0..4095
    const int b = t >> 10;
    const int s = t & 1023;
    const float* qkv = g_qkv + (size_t)t * QKV_N;

    for (int idx = threadIdx.x; idx < HIDDEN; idx += blockDim.x) {
        const int h = idx >> 7;        // head
        const int d = idx & 127;
        const size_t src = (size_t)h * HEAD_SIZE + d;
        const size_t dst = ((size_t)(b * NUM_HEADS + h) * SEQ + s) * HEAD_SIZE + d;

        float qv = qkv[src];
        float kv = qkv[src + HIDDEN];
        float vv = qkv[src + 2 * HIDDEN];

        if (d < 2 * ROT) {
            if (d < ROT) {
                const float c  = cosb[t * ROT + d];
                const float sn = sinb[t * ROT + d];
                const float q2 = qkv[src + ROT];
                const float k2 = qkv[src + HIDDEN + ROT];
                qv = qv * c - q2 * sn;
                kv = kv * c - k2 * sn;
            } else {
                const int r = d - ROT;
                const float c  = cosb[t * ROT + r];
                const float sn = sinb[t * ROT + r];
                const float q1 = qkv[src - ROT];
                const float k1 = qkv[src + HIDDEN - ROT];
                qv = q1 * sn + qv * c;
                kv = k1 * sn + kv * c;
            }
        }
        g_q[dst] = qv;
        g_k[dst] = kv;
        g_v[dst] = vv;
    }
}

// ============================================================================
// Kernel 3/4: fp32 flash attention, causal.
// Grid: (qtile=16, head=16, batch=4). Block: 256 threads = 64 rows x 4 lanes.
// Each 4-lane group owns one q row; each lane owns d = quad + 4*i (i<32):
// stride-4 partitioning makes all K/V SMEM reads bank-conflict-free
// (4 quads hit 4 distinct banks, 8 rows/warp broadcast).
// ============================================================================
#define QTILE 64
#define KTILE 32

__global__ void __launch_bounds__(256) flash_fp32()
{
    __shared__ float Ks[KTILE][HEAD_SIZE];
    __shared__ float Vs[KTILE][HEAD_SIZE];
    __shared__ float Sc[QTILE][KTILE + 1];   // +1 pad: row-varying reads conflict-free

    const int qt = blockIdx.x;
    const int h  = blockIdx.y;
    const int b  = blockIdx.z;
    const int tid  = threadIdx.x;
    const int row  = tid >> 2;     // 0..63
    const int quad = tid & 3;      // 0..3

    const float scale = 0.08838834764831845f;   // 1/sqrt(128)
    const int sq = qt * QTILE + row;            // query position in sequence
    const size_t headbase = (size_t)(b * NUM_HEADS + h) * SEQ * HEAD_SIZE;

    // q row slice into registers (stride-4 over d)
    float qr[32];
    {
        const float* qp = g_q + headbase + (size_t)sq * HEAD_SIZE;
#pragma unroll
        for (int i = 0; i < 32; ++i) qr[i] = qp[quad + 4 * i];
    }

    float o[32];
#pragma unroll
    for (int i = 0; i < 32; ++i) o[i] = 0.0f;
    float m = -1e30f, l = 0.0f;

    const int nkt = 2 * qt + 2;    // ktiles covering keys [0, (qt+1)*64)
    for (int kt = 0; kt < nkt; ++kt) {
        __syncthreads();   // previous tile fully consumed
        // cooperative load of K,V tile (32 keys x 128 dims)
        {
            const float* kg = g_k + headbase + (size_t)(kt * KTILE) * HEAD_SIZE;
            const float* vg = g_v + headbase + (size_t)(kt * KTILE) * HEAD_SIZE;
#pragma unroll
            for (int it = 0; it < 4; ++it) {
                const int flat = it * 256 + tid;      // 0..1023 float4 slots
                const int j  = flat >> 5;
                const int d4 = (flat & 31) << 2;
                *(float4*)&Ks[j][d4] = *(const float4*)(kg + (size_t)j * HEAD_SIZE + d4);
                *(float4*)&Vs[j][d4] = *(const float4*)(vg + (size_t)j * HEAD_SIZE + d4);
            }
        }
        __syncthreads();

        // Phase A: scores for this tile
        float tmax = -1e30f;
        for (int j = 0; j < KTILE; ++j) {
            float part = 0.0f;
#pragma unroll
            for (int i = 0; i < 32; ++i)
                part = fmaf(qr[i], Ks[j][quad + 4 * i], part);
            part += __shfl_xor_sync(0xffffffffu, part, 1);
            part += __shfl_xor_sync(0xffffffffu, part, 2);
            float sv = part * scale;
            if (kt * KTILE + j > sq) sv = -1e30f;    // causal mask
            tmax = fmaxf(tmax, sv);
            if (quad == 0) Sc[row][j] = sv;
        }
        __syncwarp();

        // Phase B: online softmax update + PV accumulate
        const float m_new = fmaxf(m, tmax);
        const float alpha = __expf(m - m_new);
#pragma unroll
        for (int i = 0; i < 32; ++i) o[i] *= alpha;
        float sump = 0.0f;
        for (int j = 0; j < KTILE; ++j) {
            const float p = __expf(Sc[row][j] - m_new);
            sump += p;
#pragma unroll
            for (int i = 0; i < 32; ++i)
                o[i] = fmaf(p, Vs[j][quad + 4 * i], o[i]);
        }
        l = l * alpha + sump;
        m = m_new;
    }

    // write out: [T, H*D]
    const float inv = 1.0f / l;
    const int t = b * SEQ + sq;
    float* op = g_attn + (size_t)t * HIDDEN + h * HEAD_SIZE;
#pragma unroll
    for (int i = 0; i < 32; ++i) op[quad + 4 * i] = o[i] * inv;
}

// ============================================================================
// launch
// ============================================================================
extern "C" void kernel_launch(void* const* d_in, const int* in_sizes, int n_in,
                              void* d_out, int out_size)
{
    const float* hidden  = (const float*)d_in[0];
    const float* cosb    = (const float*)d_in[1];
    const float* sinb    = (const float*)d_in[2];
    const float* W_qkv   = (const float*)d_in[3];
    const float* b_qkv   = (const float*)d_in[4];
    const float* W_dense = (const float*)d_in[5];
    const float* b_dense = (const float*)d_in[6];
    float* out = (float*)d_out;

    float *qkv_ptr = nullptr, *attn_ptr = nullptr;
    cudaGetSymbolAddress((void**)&qkv_ptr, g_qkv);
    cudaGetSymbolAddress((void**)&attn_ptr, g_attn);

    // 1) QKV projection: [4096,2048] @ [2048,6144] + b
    {
        dim3 grid(QKV_N / 128, TOTAL / 128);
        sgemm_bias<<<grid, 256>>>(hidden, W_qkv, b_qkv, qkv_ptr, TOTAL, QKV_N, HIDDEN);
    }
    // 2) rotary + split
    rope_split<<<TOTAL, 256>>>(cosb, sinb);
    // 3) causal flash attention
    {
        dim3 grid(SEQ / QTILE, NUM_HEADS, BATCH);
        flash_fp32<<<grid, 256>>>();
    }
    // 4) dense projection: [4096,2048] @ [2048,2048] + b
    {
        dim3 grid(HIDDEN / 128, TOTAL / 128);
        sgemm_bias<<<grid, 256>>>(attn_ptr, W_dense, b_dense, out, TOTAL, HIDDEN, HIDDEN);
    }
}

// round 3
// speedup vs baseline: 1.2031x; 1.2031x over previous
#include <cuda_runtime.h>
#include <math.h>

// Problem constants
#define NUM_HEADS 16
#define HEAD_SIZE 128
#define HIDDEN    2048   // NUM_HEADS*HEAD_SIZE
#define ROT       16
#define BATCH     4
#define SEQ       1024
#define TOTAL     4096   // BATCH*SEQ
#define QKV_N     6144   // 3*HIDDEN

// -------- device scratch (static; no allocation allowed) --------
__device__ float g_qkv[(size_t)TOTAL * QKV_N];            // [T, 3*H*D] post-GEMM+bias
__device__ float g_q[(size_t)TOTAL * HIDDEN];             // [B,H,S,D]
__device__ float g_k[(size_t)TOTAL * HIDDEN];             // [B,H,S,D]
__device__ float g_v[(size_t)TOTAL * HIDDEN];             // [B,H,S,D]
__device__ float g_attn[(size_t)TOTAL * HIDDEN];          // [T, H*D]

// ============================================================================
// Kernel 1/4: classic 128x128x8 SGEMM with bias epilogue. (unchanged)
// ============================================================================
__global__ void __launch_bounds__(256) sgemm_bias(
    const float* __restrict__ A, const float* __restrict__ B,
    const float* __restrict__ bias, float* __restrict__ C,
    int M, int N, int K)
{
    __shared__ float As[8][128];
    __shared__ float Bs[8][128];

    const int tid = threadIdx.x;
    const int bx = blockIdx.x;   // N tile
    const int by = blockIdx.y;   // M tile
    const int tx = tid & 15;     // 16 cols of microtiles
    const int ty = tid >> 4;     // 16 rows of microtiles

    const int aRow = tid >> 1;           // 0..127
    const int aCol = (tid & 1) << 2;     // 0 or 4
    const int bRow = tid >> 5;           // 0..7
    const int bCol = (tid & 31) << 2;    // 0..124

    const float* Ap = A + (size_t)(by * 128 + aRow) * K + aCol;
    const float* Bp = B + (size_t)bRow * N + bx * 128 + bCol;

    float acc[8][8];
#pragma unroll
    for (int i = 0; i < 8; ++i)
#pragma unroll
        for (int j = 0; j < 8; ++j) acc[i][j] = 0.0f;

    for (int k0 = 0; k0 < K; k0 += 8) {
        float4 a4 = *(const float4*)(Ap + k0);
        As[aCol + 0][aRow] = a4.x;
        As[aCol + 1][aRow] = a4.y;
        As[aCol + 2][aRow] = a4.z;
        As[aCol + 3][aRow] = a4.w;
        float4 b4 = *(const float4*)(Bp + (size_t)k0 * N);
        *(float4*)&Bs[bRow][bCol] = b4;
        __syncthreads();

#pragma unroll
        for (int kk = 0; kk < 8; ++kk) {
            float ar[8], br[8];
            *(float4*)(ar)     = *(const float4*)&As[kk][ty * 8];
            *(float4*)(ar + 4) = *(const float4*)&As[kk][ty * 8 + 4];
            *(float4*)(br)     = *(const float4*)&Bs[kk][tx * 8];
            *(float4*)(br + 4) = *(const float4*)&Bs[kk][tx * 8 + 4];
#pragma unroll
            for (int i = 0; i < 8; ++i)
#pragma unroll
                for (int j = 0; j < 8; ++j)
                    acc[i][j] = fmaf(ar[i], br[j], acc[i][j]);
        }
        __syncthreads();
    }

    const int row0 = by * 128 + ty * 8;
    const int col0 = bx * 128 + tx * 8;
    float bsv[8];
    *(float4*)(bsv)     = *(const float4*)&bias[col0];
    *(float4*)(bsv + 4) = *(const float4*)&bias[col0 + 4];
#pragma unroll
    for (int i = 0; i < 8; ++i) {
        float4 o0, o1;
        o0.x = acc[i][0] + bsv[0]; o0.y = acc[i][1] + bsv[1];
        o0.z = acc[i][2] + bsv[2]; o0.w = acc[i][3] + bsv[3];
        o1.x = acc[i][4] + bsv[4]; o1.y = acc[i][5] + bsv[5];
        o1.z = acc[i][6] + bsv[6]; o1.w = acc[i][7] + bsv[7];
        *(float4*)&C[(size_t)(row0 + i) * N + col0]     = o0;
        *(float4*)&C[(size_t)(row0 + i) * N + col0 + 4] = o1;
    }
}

// ============================================================================
// Kernel 2/4: rotary embedding + split into Q/K/V [B,H,S,D] (unchanged)
// ============================================================================
__global__ void __launch_bounds__(256) rope_split(
    const float* __restrict__ cosb, const float* __restrict__ sinb)
{
    const int t = blockIdx.x;          // token 0..4095
    const int b = t >> 10;
    const int s = t & 1023;
    const float* qkv = g_qkv + (size_t)t * QKV_N;

    for (int idx = threadIdx.x; idx < HIDDEN; idx += blockDim.x) {
        const int h = idx >> 7;        // head
        const int d = idx & 127;
        const size_t src = (size_t)h * HEAD_SIZE + d;
        const size_t dst = ((size_t)(b * NUM_HEADS + h) * SEQ + s) * HEAD_SIZE + d;

        float qv = qkv[src];
        float kv = qkv[src + HIDDEN];
        float vv = qkv[src + 2 * HIDDEN];

        if (d < 2 * ROT) {
            if (d < ROT) {
                const float c  = cosb[t * ROT + d];
                const float sn = sinb[t * ROT + d];
                const float q2 = qkv[src + ROT];
                const float k2 = qkv[src + HIDDEN + ROT];
                qv = qv * c - q2 * sn;
                kv = kv * c - k2 * sn;
            } else {
                const int r = d - ROT;
                const float c  = cosb[t * ROT + r];
                const float sn = sinb[t * ROT + r];
                const float q1 = qkv[src - ROT];
                const float k1 = qkv[src + HIDDEN - ROT];
                qv = q1 * sn + qv * c;
                kv = k1 * sn + kv * c;
            }
        }
        g_q[dst] = qv;
        g_k[dst] = kv;
        g_v[dst] = vv;
    }
}

// ============================================================================
// Kernel 3/4: fp32 flash attention v2 — register-blocked micro-GEMMs.
// Block: 256 threads. QTILE=KTILE=64. SMEM-staged Q/K/V tiles, score tile.
// Score pass: 4x4 microtiles (rows (tid>>4)*4.., cols (tid&15)+16*jc).
// PV pass: warp w owns q-rows w*8..w*8+7, lane owns dims (lane*4..+3).
// FIX vs round 2: Q-tile load is 2048 float4 slots -> 8 iterations (was 32,
// which overran Qs[64] rows by 4x -> illegal memory access).
// ============================================================================
#define FQT 64
#define FKT 64
#define LDT 132     // padded row stride for Q/K/V tiles (floats)
#define LDS 68      // padded row stride for score tile

struct FlashSmem {
    float Qs[FQT][LDT];
    float Ks[FKT][LDT];
    float Vs[FKT][LDT];
    float Sc[FQT][LDS];
    float m_s[FQT];
    float l_s[FQT];
    float a_s[FQT];
};

__global__ void __launch_bounds__(256) flash_v2()
{
    extern __shared__ char sraw[];
    FlashSmem& S = *reinterpret_cast<FlashSmem*>(sraw);

    const int qt = blockIdx.x;
    const int h  = blockIdx.y;
    const int b  = blockIdx.z;
    const int tid = threadIdx.x;
    const size_t headbase = (size_t)(b * NUM_HEADS + h) * SEQ * HEAD_SIZE;
    const float scale = 0.08838834764831845f;   // 1/sqrt(128)

    // ---- load Q tile (pre-scaled): 64 rows x 32 float4 = 2048 slots ----
    {
        const float* qg = g_q + headbase + (size_t)(qt * FQT) * HEAD_SIZE;
#pragma unroll
        for (int it = 0; it < 8; ++it) {
            const int flat = it * 256 + tid;      // 0..2047
            const int r = flat >> 5;              // 0..63
            const int d4 = (flat & 31) << 2;      // 0..124
            float4 v = *(const float4*)(qg + (size_t)r * HEAD_SIZE + d4);
            v.x *= scale; v.y *= scale; v.z *= scale; v.w *= scale;
            *(float4*)&S.Qs[r][d4] = v;
        }
    }
    if (tid < FQT) { S.m_s[tid] = -1e30f; S.l_s[tid] = 0.0f; }

    // PV accumulator layout
    const int orow0 = (tid >> 5) * 8;     // 8 q-rows per warp
    const int od    = (tid & 31) << 2;    // 4 dims per lane
    float o[32];
#pragma unroll
    for (int i = 0; i < 32; ++i) o[i] = 0.0f;

    // score microtile layout
    const int sr0 = (tid >> 4) << 2;      // 4 consecutive q-rows
    const int sc0 = tid & 15;             // cols sc0 + 16*jc

    const int nkt = qt + 1;
    for (int kt = 0; kt < nkt; ++kt) {
        __syncthreads();   // previous PV done before overwriting tiles
        // ---- load K,V tile: 64 rows x 32 float4 = 2048 slots each ----
        {
            const float* kg = g_k + headbase + (size_t)(kt * FKT) * HEAD_SIZE;
            const float* vg = g_v + headbase + (size_t)(kt * FKT) * HEAD_SIZE;
#pragma unroll
            for (int it = 0; it < 8; ++it) {
                const int flat = it * 256 + tid;
                const int r = flat >> 5;
                const int d4 = (flat & 31) << 2;
                *(float4*)&S.Ks[r][d4] = *(const float4*)(kg + (size_t)r * HEAD_SIZE + d4);
                *(float4*)&S.Vs[r][d4] = *(const float4*)(vg + (size_t)r * HEAD_SIZE + d4);
            }
        }
        __syncthreads();

        // ---- score pass: 4x4 register microtile over d ----
        {
            float acc[4][4];
#pragma unroll
            for (int i = 0; i < 4; ++i)
#pragma unroll
                for (int j = 0; j < 4; ++j) acc[i][j] = 0.0f;

#pragma unroll 4
            for (int d = 0; d < HEAD_SIZE; d += 4) {
                float4 q0 = *(const float4*)&S.Qs[sr0 + 0][d];
                float4 q1 = *(const float4*)&S.Qs[sr0 + 1][d];
                float4 q2 = *(const float4*)&S.Qs[sr0 + 2][d];
                float4 q3 = *(const float4*)&S.Qs[sr0 + 3][d];
                float4 k0 = *(const float4*)&S.Ks[sc0 +  0][d];
                float4 k1 = *(const float4*)&S.Ks[sc0 + 16][d];
                float4 k2 = *(const float4*)&S.Ks[sc0 + 32][d];
                float4 k3 = *(const float4*)&S.Ks[sc0 + 48][d];
#define SDOT(i, QV)  \
    acc[i][0] = fmaf(QV.x, k0.x, acc[i][0]); acc[i][0] = fmaf(QV.y, k0.y, acc[i][0]); \
    acc[i][0] = fmaf(QV.z, k0.z, acc[i][0]); acc[i][0] = fmaf(QV.w, k0.w, acc[i][0]); \
    acc[i][1] = fmaf(QV.x, k1.x, acc[i][1]); acc[i][1] = fmaf(QV.y, k1.y, acc[i][1]); \
    acc[i][1] = fmaf(QV.z, k1.z, acc[i][1]); acc[i][1] = fmaf(QV.w, k1.w, acc[i][1]); \
    acc[i][2] = fmaf(QV.x, k2.x, acc[i][2]); acc[i][2] = fmaf(QV.y, k2.y, acc[i][2]); \
    acc[i][2] = fmaf(QV.z, k2.z, acc[i][2]); acc[i][2] = fmaf(QV.w, k2.w, acc[i][2]); \
    acc[i][3] = fmaf(QV.x, k3.x, acc[i][3]); acc[i][3] = fmaf(QV.y, k3.y, acc[i][3]); \
    acc[i][3] = fmaf(QV.z, k3.z, acc[i][3]); acc[i][3] = fmaf(QV.w, k3.w, acc[i][3]);
                SDOT(0, q0) SDOT(1, q1) SDOT(2, q2) SDOT(3, q3)
#undef SDOT
            }
#pragma unroll
            for (int i = 0; i < 4; ++i) {
                S.Sc[sr0 + i][sc0 +  0] = acc[i][0];
                S.Sc[sr0 + i][sc0 + 16] = acc[i][1];
                S.Sc[sr0 + i][sc0 + 32] = acc[i][2];
                S.Sc[sr0 + i][sc0 + 48] = acc[i][3];
            }
        }
        __syncthreads();

        // ---- online softmax (4 threads per row) ----
        {
            const int row = tid >> 2;
            const int sub = tid & 3;
            const int sq  = qt * FQT + row;
            const int c0  = sub * 16;
            float sv[16];
            float mx = -1e30f;
#pragma unroll
            for (int jj = 0; jj < 16; ++jj) {
                const int cg = kt * FKT + c0 + jj;
                float s = S.Sc[row][c0 + jj];
                s = (cg > sq) ? -1e30f : s;
                sv[jj] = s;
                mx = fmaxf(mx, s);
            }
            mx = fmaxf(mx, __shfl_xor_sync(0xffffffffu, mx, 1));
            mx = fmaxf(mx, __shfl_xor_sync(0xffffffffu, mx, 2));
            const float m_old = S.m_s[row];
            const float m_new = fmaxf(m_old, mx);
            float sum = 0.0f;
#pragma unroll
            for (int jj = 0; jj < 16; ++jj) {
                const float p = __expf(sv[jj] - m_new);
                S.Sc[row][c0 + jj] = p;
                sum += p;
            }
            sum += __shfl_xor_sync(0xffffffffu, sum, 1);
            sum += __shfl_xor_sync(0xffffffffu, sum, 2);
            __syncwarp();   // all lanes done reading m_s/l_s before sub0 writes
            if (sub == 0) {
                const float alpha = __expf(m_old - m_new);
                S.a_s[row] = alpha;
                S.m_s[row] = m_new;
                S.l_s[row] = S.l_s[row] * alpha + sum;
            }
        }
        __syncthreads();

        // ---- PV pass ----
        {
            float al[8];
#pragma unroll
            for (int i = 0; i < 8; ++i) al[i] = S.a_s[orow0 + i];
#pragma unroll
            for (int i = 0; i < 8; ++i) {
                o[i * 4 + 0] *= al[i]; o[i * 4 + 1] *= al[i];
                o[i * 4 + 2] *= al[i]; o[i * 4 + 3] *= al[i];
            }
#pragma unroll 2
            for (int j = 0; j < FKT; ++j) {
                const float4 v = *(const float4*)&S.Vs[j][od];
#pragma unroll
                for (int i = 0; i < 8; ++i) {
                    const float p = S.Sc[orow0 + i][j];
                    o[i * 4 + 0] = fmaf(p, v.x, o[i * 4 + 0]);
                    o[i * 4 + 1] = fmaf(p, v.y, o[i * 4 + 1]);
                    o[i * 4 + 2] = fmaf(p, v.z, o[i * 4 + 2]);
                    o[i * 4 + 3] = fmaf(p, v.w, o[i * 4 + 3]);
                }
            }
        }
    }

    // ---- epilogue: normalize and write [T, H*D] ----
    {
        const int t0 = b * SEQ + qt * FQT;
#pragma unroll
        for (int i = 0; i < 8; ++i) {
            const int row = orow0 + i;
            const float inv = 1.0f / S.l_s[row];
            float4 ov;
            ov.x = o[i * 4 + 0] * inv; ov.y = o[i * 4 + 1] * inv;
            ov.z = o[i * 4 + 2] * inv; ov.w = o[i * 4 + 3] * inv;
            *(float4*)&g_attn[(size_t)(t0 + row) * HIDDEN + h * HEAD_SIZE + od] = ov;
        }
    }
}

// ============================================================================
// launch
// ============================================================================
extern "C" void kernel_launch(void* const* d_in, const int* in_sizes, int n_in,
                              void* d_out, int out_size)
{
    const float* hidden  = (const float*)d_in[0];
    const float* cosb    = (const float*)d_in[1];
    const float* sinb    = (const float*)d_in[2];
    const float* W_qkv   = (const float*)d_in[3];
    const float* b_qkv   = (const float*)d_in[4];
    const float* W_dense = (const float*)d_in[5];
    const float* b_dense = (const float*)d_in[6];
    float* out = (float*)d_out;

    float *qkv_ptr = nullptr, *attn_ptr = nullptr;
    cudaGetSymbolAddress((void**)&qkv_ptr, g_qkv);
    cudaGetSymbolAddress((void**)&attn_ptr, g_attn);

    cudaFuncSetAttribute(flash_v2, cudaFuncAttributeMaxDynamicSharedMemorySize,
                         (int)sizeof(FlashSmem));

    // 1) QKV projection: [4096,2048] @ [2048,6144] + b
    {
        dim3 grid(QKV_N / 128, TOTAL / 128);
        sgemm_bias<<<grid, 256>>>(hidden, W_qkv, b_qkv, qkv_ptr, TOTAL, QKV_N, HIDDEN);
    }
    // 2) rotary + split
    rope_split<<<TOTAL, 256>>>(cosb, sinb);
    // 3) causal flash attention v2
    {
        dim3 grid(SEQ / FQT, NUM_HEADS, BATCH);
        flash_v2<<<grid, 256, sizeof(FlashSmem)>>>();
    }
    // 4) dense projection: [4096,2048] @ [2048,2048] + b
    {
        dim3 grid(HIDDEN / 128, TOTAL / 128);
        sgemm_bias<<<grid, 256>>>(attn_ptr, W_dense, b_dense, out, TOTAL, HIDDEN, HIDDEN);
    }
}

// round 5
// speedup vs baseline: 2.8294x; 2.3517x over previous
#include <cuda_runtime.h>
#include <cuda.h>
#include <math.h>
#include <stdint.h>

// Problem constants
#define NUM_HEADS 16
#define HEAD_SIZE 128
#define HIDDEN    2048
#define ROT       16
#define BATCH     4
#define SEQ       1024
#define TOTAL     4096
#define QKV_N     6144

// -------- device scratch --------
__device__ float g_qkv[(size_t)TOTAL * QKV_N];
__device__ float g_q[(size_t)TOTAL * HIDDEN];
__device__ float g_k[(size_t)TOTAL * HIDDEN];
__device__ float g_v[(size_t)TOTAL * HIDDEN];
__device__ float g_attn[(size_t)TOTAL * HIDDEN];
__device__ float g_wqkvT[(size_t)QKV_N * HIDDEN];        // W_qkv^T [N][K], tf32-rounded
__device__ float g_wdenseT[(size_t)HIDDEN * HIDDEN];     // W_dense^T [N][K], tf32-rounded

// ============================================================================
// helpers
// ============================================================================
__device__ __forceinline__ uint32_t smem_u32(const void* p) {
    uint32_t a;
    asm("{ .reg .u64 t; cvta.to.shared.u64 t, %1; cvt.u32.u64 %0, t; }" : "=r"(a) : "l"(p));
    return a;
}
__device__ __forceinline__ float rn_tf32(float x) {
    uint32_t b;
    asm("cvt.rna.tf32.f32 %0, %1;" : "=r"(b) : "f"(x));
    return __uint_as_float(b);
}
__device__ __forceinline__ uint32_t rn_tf32_bits(float x) {
    uint32_t b;
    asm("cvt.rna.tf32.f32 %0, %1;" : "=r"(b) : "f"(x));
    return b;
}

// m16n8k8 tf32 HMMA (base-target instruction, works on compute_103)
__device__ __forceinline__ void mma_tf32(float* c, const uint32_t* a, const uint32_t* b) {
    asm volatile(
        "mma.sync.aligned.m16n8k8.row.col.f32.tf32.tf32.f32 "
        "{%0,%1,%2,%3}, {%4,%5,%6,%7}, {%8,%9}, {%0,%1,%2,%3};"
        : "+f"(c[0]), "+f"(c[1]), "+f"(c[2]), "+f"(c[3])
        : "r"(a[0]), "r"(a[1]), "r"(a[2]), "r"(a[3]), "r"(b[0]), "r"(b[1]));
}

// ============================================================================
// tf32 mma.sync GEMM: C[M,N] = A[M,K] @ Bt[N,K]^T + bias
// 128x128 CTA tile, 8 warps (2x4), warp tile 64x32, K-chunk 16, double-buffer.
// A is raw fp32 (rounded to tf32 in-register); Bt is pre-rounded.
// ============================================================================
#define KCH 16
#define LDP 20      // smem row stride (floats) -> conflict-free frag loads

__global__ void __launch_bounds__(256, 2) gemm_tf32_mma(
    const float* __restrict__ A, const float* __restrict__ Bt,
    const float* __restrict__ bias, float* __restrict__ C,
    int M, int N, int K)
{
    __shared__ float As[2][128][LDP];
    __shared__ float Bs[2][128][LDP];

    const int tid  = threadIdx.x;
    const int wid  = tid >> 5;
    const int lane = tid & 31;
    const int wm = wid >> 2;          // 0..1
    const int wn = wid & 3;           // 0..3
    const int qr = lane >> 2;         // 0..7
    const int qc = lane & 3;          // 0..3
    const int m0 = blockIdx.y * 128;
    const int n0 = blockIdx.x * 128;

    float acc[4][4][4];
#pragma unroll
    for (int i = 0; i < 4; ++i)
#pragma unroll
        for (int j = 0; j < 4; ++j)
#pragma unroll
            for (int k = 0; k < 4; ++k) acc[i][j][k] = 0.0f;

    // async copy of one K-chunk into stage s
    auto load_chunk = [&](int c, int s) {
        const int kbase = c * KCH;
#pragma unroll
        for (int it = 0; it < 2; ++it) {
            const int idx = it * 256 + tid;   // 0..511
            const int row = idx >> 2;         // 0..127
            const int c4  = (idx & 3) << 2;   // 0,4,8,12
            const float* srcA = A  + (size_t)(m0 + row) * K + kbase + c4;
            const float* srcB = Bt + (size_t)(n0 + row) * K + kbase + c4;
            const uint32_t da = smem_u32(&As[s][row][c4]);
            const uint32_t db = smem_u32(&Bs[s][row][c4]);
            asm volatile("cp.async.cg.shared.global [%0], [%1], 16;" :: "r"(da), "l"(srcA) : "memory");
            asm volatile("cp.async.cg.shared.global [%0], [%1], 16;" :: "r"(db), "l"(srcB) : "memory");
        }
        asm volatile("cp.async.commit_group;" ::: "memory");
    };

    const int NCH = K / KCH;
    load_chunk(0, 0);

    for (int c = 0; c < NCH; ++c) {
        const int s = c & 1;
        if (c + 1 < NCH) {
            load_chunk(c + 1, (c + 1) & 1);
            asm volatile("cp.async.wait_group 1;" ::: "memory");
        } else {
            asm volatile("cp.async.wait_group 0;" ::: "memory");
        }
        __syncthreads();

#pragma unroll
        for (int ks = 0; ks < 2; ++ks) {
            const int k0 = ks * 8;
            uint32_t af[4][4];
#pragma unroll
            for (int mt = 0; mt < 4; ++mt) {
                const int r = wm * 64 + mt * 16 + qr;
                af[mt][0] = rn_tf32_bits(As[s][r    ][k0     + qc]);
                af[mt][1] = rn_tf32_bits(As[s][r + 8][k0     + qc]);
                af[mt][2] = rn_tf32_bits(As[s][r    ][k0 + 4 + qc]);
                af[mt][3] = rn_tf32_bits(As[s][r + 8][k0 + 4 + qc]);
            }
            uint32_t bf[4][2];
#pragma unroll
            for (int nt = 0; nt < 4; ++nt) {
                const int rn = wn * 32 + nt * 8 + qr;
                bf[nt][0] = __float_as_uint(Bs[s][rn][k0     + qc]);
                bf[nt][1] = __float_as_uint(Bs[s][rn][k0 + 4 + qc]);
            }
#pragma unroll
            for (int mt = 0; mt < 4; ++mt)
#pragma unroll
                for (int nt = 0; nt < 4; ++nt)
                    mma_tf32(acc[mt][nt], af[mt], bf[nt]);
        }
        __syncthreads();   // stage s fully consumed before chunk c+2 overwrites it
    }

    // epilogue: c0,c1 -> (row, col..col+1); c2,c3 -> (row+8, ...)
#pragma unroll
    for (int mt = 0; mt < 4; ++mt) {
        const int row = m0 + wm * 64 + mt * 16 + qr;
#pragma unroll
        for (int nt = 0; nt < 4; ++nt) {
            const int col = n0 + wn * 32 + nt * 8 + 2 * qc;
            const float2 bv = *(const float2*)&bias[col];
            float2 o0, o1;
            o0.x = acc[mt][nt][0] + bv.x; o0.y = acc[mt][nt][1] + bv.y;
            o1.x = acc[mt][nt][2] + bv.x; o1.y = acc[mt][nt][3] + bv.y;
            *(float2*)&C[(size_t)row * N + col]       = o0;
            *(float2*)&C[(size_t)(row + 8) * N + col] = o1;
        }
    }
}

// ============================================================================
// Transpose + tf32 rounding: dst[Ccols][R] = rn(src[R][Ccols])
// ============================================================================
__global__ void __launch_bounds__(256) transpose_rn(
    const float* __restrict__ src, float* __restrict__ dst, int R, int Ccols)
{
    __shared__ float t[32][33];
    const int tx = threadIdx.x & 31;
    const int ty = threadIdx.x >> 5;          // 0..7
    const int c0 = blockIdx.x * 32;
    const int r0 = blockIdx.y * 32;
#pragma unroll
    for (int j = 0; j < 4; ++j)
        t[ty + 8 * j][tx] = src[(size_t)(r0 + ty + 8 * j) * Ccols + c0 + tx];
    __syncthreads();
#pragma unroll
    for (int j = 0; j < 4; ++j)
        dst[(size_t)(c0 + ty + 8 * j) * R + r0 + tx] = rn_tf32(t[tx][ty + 8 * j]);
}

// ============================================================================
// rotary embedding + split into Q/K/V [B,H,S,D]
// ============================================================================
__global__ void __launch_bounds__(256) rope_split(
    const float* __restrict__ cosb, const float* __restrict__ sinb)
{
    const int t = blockIdx.x;
    const int b = t >> 10;
    const int s = t & 1023;
    const float* qkv = g_qkv + (size_t)t * QKV_N;

    for (int idx = threadIdx.x; idx < HIDDEN; idx += blockDim.x) {
        const int h = idx >> 7;
        const int d = idx & 127;
        const size_t src = (size_t)h * HEAD_SIZE + d;
        const size_t dst = ((size_t)(b * NUM_HEADS + h) * SEQ + s) * HEAD_SIZE + d;

        float qv = qkv[src];
        float kv = qkv[src + HIDDEN];
        float vv = qkv[src + 2 * HIDDEN];

        if (d < 2 * ROT) {
            if (d < ROT) {
                const float c  = cosb[t * ROT + d];
                const float sn = sinb[t * ROT + d];
                const float q2 = qkv[src + ROT];
                const float k2 = qkv[src + HIDDEN + ROT];
                qv = qv * c - q2 * sn;
                kv = kv * c - k2 * sn;
            } else {
                const int r = d - ROT;
                const float c  = cosb[t * ROT + r];
                const float sn = sinb[t * ROT + r];
                const float q1 = qkv[src - ROT];
                const float k1 = qkv[src + HIDDEN - ROT];
                qv = q1 * sn + qv * c;
                kv = k1 * sn + kv * c;
            }
        }
        g_q[dst] = qv;
        g_k[dst] = kv;
        g_v[dst] = vv;
    }
}

// ============================================================================
// fp32 flash attention v2 (unchanged; output tf32-rounded for dense GEMM,
// which also rounds in-register — double rounding is idempotent)
// ============================================================================
#define FQT 64
#define FKT 64
#define LDT 132
#define LDS 68

struct FlashSmem {
    float Qs[FQT][LDT];
    float Ks[FKT][LDT];
    float Vs[FKT][LDT];
    float Sc[FQT][LDS];
    float m_s[FQT];
    float l_s[FQT];
    float a_s[FQT];
};

__global__ void __launch_bounds__(256) flash_v2()
{
    extern __shared__ char sraw[];
    FlashSmem& S = *reinterpret_cast<FlashSmem*>(sraw);

    const int qt = blockIdx.x;
    const int h  = blockIdx.y;
    const int b  = blockIdx.z;
    const int tid = threadIdx.x;
    const size_t headbase = (size_t)(b * NUM_HEADS + h) * SEQ * HEAD_SIZE;
    const float scale = 0.08838834764831845f;

    {
        const float* qg = g_q + headbase + (size_t)(qt * FQT) * HEAD_SIZE;
#pragma unroll
        for (int it = 0; it < 8; ++it) {
            const int flat = it * 256 + tid;
            const int r = flat >> 5;
            const int d4 = (flat & 31) << 2;
            float4 v = *(const float4*)(qg + (size_t)r * HEAD_SIZE + d4);
            v.x *= scale; v.y *= scale; v.z *= scale; v.w *= scale;
            *(float4*)&S.Qs[r][d4] = v;
        }
    }
    if (tid < FQT) { S.m_s[tid] = -1e30f; S.l_s[tid] = 0.0f; }

    const int orow0 = (tid >> 5) * 8;
    const int od    = (tid & 31) << 2;
    float o[32];
#pragma unroll
    for (int i = 0; i < 32; ++i) o[i] = 0.0f;

    const int sr0 = (tid >> 4) << 2;
    const int sc0 = tid & 15;

    const int nkt = qt + 1;
    for (int kt = 0; kt < nkt; ++kt) {
        __syncthreads();
        {
            const float* kg = g_k + headbase + (size_t)(kt * FKT) * HEAD_SIZE;
            const float* vg = g_v + headbase + (size_t)(kt * FKT) * HEAD_SIZE;
#pragma unroll
            for (int it = 0; it < 8; ++it) {
                const int flat = it * 256 + tid;
                const int r = flat >> 5;
                const int d4 = (flat & 31) << 2;
                *(float4*)&S.Ks[r][d4] = *(const float4*)(kg + (size_t)r * HEAD_SIZE + d4);
                *(float4*)&S.Vs[r][d4] = *(const float4*)(vg + (size_t)r * HEAD_SIZE + d4);
            }
        }
        __syncthreads();

        {
            float acc[4][4];
#pragma unroll
            for (int i = 0; i < 4; ++i)
#pragma unroll
                for (int j = 0; j < 4; ++j) acc[i][j] = 0.0f;

#pragma unroll 4
            for (int d = 0; d < HEAD_SIZE; d += 4) {
                float4 q0 = *(const float4*)&S.Qs[sr0 + 0][d];
                float4 q1 = *(const float4*)&S.Qs[sr0 + 1][d];
                float4 q2 = *(const float4*)&S.Qs[sr0 + 2][d];
                float4 q3 = *(const float4*)&S.Qs[sr0 + 3][d];
                float4 k0 = *(const float4*)&S.Ks[sc0 +  0][d];
                float4 k1 = *(const float4*)&S.Ks[sc0 + 16][d];
                float4 k2 = *(const float4*)&S.Ks[sc0 + 32][d];
                float4 k3 = *(const float4*)&S.Ks[sc0 + 48][d];
#define SDOT(i, QV)  \
    acc[i][0] = fmaf(QV.x, k0.x, acc[i][0]); acc[i][0] = fmaf(QV.y, k0.y, acc[i][0]); \
    acc[i][0] = fmaf(QV.z, k0.z, acc[i][0]); acc[i][0] = fmaf(QV.w, k0.w, acc[i][0]); \
    acc[i][1] = fmaf(QV.x, k1.x, acc[i][1]); acc[i][1] = fmaf(QV.y, k1.y, acc[i][1]); \
    acc[i][1] = fmaf(QV.z, k1.z, acc[i][1]); acc[i][1] = fmaf(QV.w, k1.w, acc[i][1]); \
    acc[i][2] = fmaf(QV.x, k2.x, acc[i][2]); acc[i][2] = fmaf(QV.y, k2.y, acc[i][2]); \
    acc[i][2] = fmaf(QV.z, k2.z, acc[i][2]); acc[i][2] = fmaf(QV.w, k2.w, acc[i][2]); \
    acc[i][3] = fmaf(QV.x, k3.x, acc[i][3]); acc[i][3] = fmaf(QV.y, k3.y, acc[i][3]); \
    acc[i][3] = fmaf(QV.z, k3.z, acc[i][3]); acc[i][3] = fmaf(QV.w, k3.w, acc[i][3]);
                SDOT(0, q0) SDOT(1, q1) SDOT(2, q2) SDOT(3, q3)
#undef SDOT
            }
#pragma unroll
            for (int i = 0; i < 4; ++i) {
                S.Sc[sr0 + i][sc0 +  0] = acc[i][0];
                S.Sc[sr0 + i][sc0 + 16] = acc[i][1];
                S.Sc[sr0 + i][sc0 + 32] = acc[i][2];
                S.Sc[sr0 + i][sc0 + 48] = acc[i][3];
            }
        }
        __syncthreads();

        {
            const int row = tid >> 2;
            const int sub = tid & 3;
            const int sq  = qt * FQT + row;
            const int c0  = sub * 16;
            float sv[16];
            float mx = -1e30f;
#pragma unroll
            for (int jj = 0; jj < 16; ++jj) {
                const int cg = kt * FKT + c0 + jj;
                float s = S.Sc[row][c0 + jj];
                s = (cg > sq) ? -1e30f : s;
                sv[jj] = s;
                mx = fmaxf(mx, s);
            }
            mx = fmaxf(mx, __shfl_xor_sync(0xffffffffu, mx, 1));
            mx = fmaxf(mx, __shfl_xor_sync(0xffffffffu, mx, 2));
            const float m_old = S.m_s[row];
            const float m_new = fmaxf(m_old, mx);
            float sum = 0.0f;
#pragma unroll
            for (int jj = 0; jj < 16; ++jj) {
                const float p = __expf(sv[jj] - m_new);
                S.Sc[row][c0 + jj] = p;
                sum += p;
            }
            sum += __shfl_xor_sync(0xffffffffu, sum, 1);
            sum += __shfl_xor_sync(0xffffffffu, sum, 2);
            __syncwarp();
            if (sub == 0) {
                const float alpha = __expf(m_old - m_new);
                S.a_s[row] = alpha;
                S.m_s[row] = m_new;
                S.l_s[row] = S.l_s[row] * alpha + sum;
            }
        }
        __syncthreads();

        {
            float al[8];
#pragma unroll
            for (int i = 0; i < 8; ++i) al[i] = S.a_s[orow0 + i];
#pragma unroll
            for (int i = 0; i < 8; ++i) {
                o[i * 4 + 0] *= al[i]; o[i * 4 + 1] *= al[i];
                o[i * 4 + 2] *= al[i]; o[i * 4 + 3] *= al[i];
            }
#pragma unroll 2
            for (int j = 0; j < FKT; ++j) {
                const float4 v = *(const float4*)&S.Vs[j][od];
#pragma unroll
                for (int i = 0; i < 8; ++i) {
                    const float p = S.Sc[orow0 + i][j];
                    o[i * 4 + 0] = fmaf(p, v.x, o[i * 4 + 0]);
                    o[i * 4 + 1] = fmaf(p, v.y, o[i * 4 + 1]);
                    o[i * 4 + 2] = fmaf(p, v.z, o[i * 4 + 2]);
                    o[i * 4 + 3] = fmaf(p, v.w, o[i * 4 + 3]);
                }
            }
        }
    }

    {
        const int t0 = b * SEQ + qt * FQT;
#pragma unroll
        for (int i = 0; i < 8; ++i) {
            const int row = orow0 + i;
            const float inv = 1.0f / S.l_s[row];
            float4 ov;
            ov.x = rn_tf32(o[i * 4 + 0] * inv);
            ov.y = rn_tf32(o[i * 4 + 1] * inv);
            ov.z = rn_tf32(o[i * 4 + 2] * inv);
            ov.w = rn_tf32(o[i * 4 + 3] * inv);
            *(float4*)&g_attn[(size_t)(t0 + row) * HIDDEN + h * HEAD_SIZE + od] = ov;
        }
    }
}

// ============================================================================
// launch
// ============================================================================
extern "C" void kernel_launch(void* const* d_in, const int* in_sizes, int n_in,
                              void* d_out, int out_size)
{
    const float* hidden  = (const float*)d_in[0];
    const float* cosb    = (const float*)d_in[1];
    const float* sinb    = (const float*)d_in[2];
    const float* W_qkv   = (const float*)d_in[3];
    const float* b_qkv   = (const float*)d_in[4];
    const float* W_dense = (const float*)d_in[5];
    const float* b_dense = (const float*)d_in[6];
    float* out = (float*)d_out;

    float *qkv_ptr, *attn_ptr, *wqkvT_ptr, *wdenseT_ptr;
    cudaGetSymbolAddress((void**)&qkv_ptr, g_qkv);
    cudaGetSymbolAddress((void**)&attn_ptr, g_attn);
    cudaGetSymbolAddress((void**)&wqkvT_ptr, g_wqkvT);
    cudaGetSymbolAddress((void**)&wdenseT_ptr, g_wdenseT);

    cudaFuncSetAttribute(flash_v2, cudaFuncAttributeMaxDynamicSharedMemorySize,
                         (int)sizeof(FlashSmem));

    // 0) weight prep: transpose + tf32 rounding (B operands)
    transpose_rn<<<dim3(QKV_N / 32, HIDDEN / 32), 256>>>(W_qkv, wqkvT_ptr, HIDDEN, QKV_N);
    transpose_rn<<<dim3(HIDDEN / 32, HIDDEN / 32), 256>>>(W_dense, wdenseT_ptr, HIDDEN, HIDDEN);

    // 1) QKV projection (tf32 mma.sync): [4096,2048] @ [2048,6144] + b
    gemm_tf32_mma<<<dim3(QKV_N / 128, TOTAL / 128), 256>>>(
        hidden, wqkvT_ptr, b_qkv, qkv_ptr, TOTAL, QKV_N, HIDDEN);
    // 2) rotary + split
    rope_split<<<TOTAL, 256>>>(cosb, sinb);
    // 3) causal flash attention (fp32)
    flash_v2<<<dim3(SEQ / FQT, NUM_HEADS, BATCH), 256, sizeof(FlashSmem)>>>();
    // 4) dense projection (tf32 mma.sync): [4096,2048] @ [2048,2048] + b
    gemm_tf32_mma<<<dim3(HIDDEN / 128, TOTAL / 128), 256>>>(
        attn_ptr, wdenseT_ptr, b_dense, out, TOTAL, HIDDEN, HIDDEN);
}

// round 6
// speedup vs baseline: 3.5727x; 1.2627x over previous
#include <cuda_runtime.h>
#include <cuda.h>
#include <math.h>
#include <stdint.h>

// Problem constants
#define NUM_HEADS 16
#define HEAD_SIZE 128
#define HIDDEN    2048
#define ROT       16
#define BATCH     4
#define SEQ       1024
#define TOTAL     4096
#define QKV_N     6144

// -------- device scratch --------
__device__ float g_qkv[(size_t)TOTAL * QKV_N];
__device__ float g_q[(size_t)TOTAL * HIDDEN];
__device__ float g_k[(size_t)TOTAL * HIDDEN];
__device__ float g_v[(size_t)TOTAL * HIDDEN];
__device__ float g_vt[(size_t)BATCH * NUM_HEADS * HEAD_SIZE * SEQ];  // [B,H,D,S] tf32
__device__ float g_attn[(size_t)TOTAL * HIDDEN];
__device__ float g_wqkvT[(size_t)QKV_N * HIDDEN];
__device__ float g_wdenseT[(size_t)HIDDEN * HIDDEN];

// ============================================================================
// helpers
// ============================================================================
__device__ __forceinline__ uint32_t smem_u32(const void* p) {
    uint32_t a;
    asm("{ .reg .u64 t; cvta.to.shared.u64 t, %1; cvt.u32.u64 %0, t; }" : "=r"(a) : "l"(p));
    return a;
}
__device__ __forceinline__ float rn_tf32(float x) {
    uint32_t b;
    asm("cvt.rna.tf32.f32 %0, %1;" : "=r"(b) : "f"(x));
    return __uint_as_float(b);
}
__device__ __forceinline__ uint32_t rn_tf32_bits(float x) {
    uint32_t b;
    asm("cvt.rna.tf32.f32 %0, %1;" : "=r"(b) : "f"(x));
    return b;
}
__device__ __forceinline__ void mma_tf32(float* c, const uint32_t* a, const uint32_t* b) {
    asm volatile(
        "mma.sync.aligned.m16n8k8.row.col.f32.tf32.tf32.f32 "
        "{%0,%1,%2,%3}, {%4,%5,%6,%7}, {%8,%9}, {%0,%1,%2,%3};"
        : "+f"(c[0]), "+f"(c[1]), "+f"(c[2]), "+f"(c[3])
        : "r"(a[0]), "r"(a[1]), "r"(a[2]), "r"(a[3]), "r"(b[0]), "r"(b[1]));
}

// ============================================================================
// tf32 mma.sync GEMM: C[M,N] = A[M,K] @ Bt[N,K]^T + bias
// 128x128 CTA tile, 8 warps (2x4), warp tile 64x32, K-chunk 32, double-buffer.
// ============================================================================
#define KCH 32
#define LDP 36                        // smem row stride (floats)
#define GEMM_STAGE (128 * LDP)        // 4608 floats per stage per matrix
#define GEMM_SMEM_BYTES (2 * GEMM_STAGE * 2 * 4)   // 73728

__global__ void __launch_bounds__(256, 2) gemm_tf32_mma(
    const float* __restrict__ A, const float* __restrict__ Bt,
    const float* __restrict__ bias, float* __restrict__ C,
    int M, int N, int K)
{
    extern __shared__ float gsm[];
    float* As = gsm;                       // [2][128][LDP]
    float* Bs = gsm + 2 * GEMM_STAGE;      // [2][128][LDP]

    const int tid  = threadIdx.x;
    const int wid  = tid >> 5;
    const int lane = tid & 31;
    const int wm = wid >> 2;          // 0..1
    const int wn = wid & 3;           // 0..3
    const int qr = lane >> 2;         // 0..7
    const int qc = lane & 3;          // 0..3
    const int m0 = blockIdx.y * 128;
    const int n0 = blockIdx.x * 128;

    float acc[4][4][4];
#pragma unroll
    for (int i = 0; i < 4; ++i)
#pragma unroll
        for (int j = 0; j < 4; ++j)
#pragma unroll
            for (int k = 0; k < 4; ++k) acc[i][j][k] = 0.0f;

    auto load_chunk = [&](int c, int s) {
        const int kbase = c * KCH;
#pragma unroll
        for (int it = 0; it < 4; ++it) {
            const int idx = it * 256 + tid;   // 0..1023
            const int row = idx >> 3;         // 0..127
            const int c4  = (idx & 7) << 2;   // 0..28
            const float* srcA = A  + (size_t)(m0 + row) * K + kbase + c4;
            const float* srcB = Bt + (size_t)(n0 + row) * K + kbase + c4;
            const uint32_t da = smem_u32(&As[s * GEMM_STAGE + row * LDP + c4]);
            const uint32_t db = smem_u32(&Bs[s * GEMM_STAGE + row * LDP + c4]);
            asm volatile("cp.async.cg.shared.global [%0], [%1], 16;" :: "r"(da), "l"(srcA) : "memory");
            asm volatile("cp.async.cg.shared.global [%0], [%1], 16;" :: "r"(db), "l"(srcB) : "memory");
        }
        asm volatile("cp.async.commit_group;" ::: "memory");
    };

    const int NCH = K / KCH;
    load_chunk(0, 0);

    for (int c = 0; c < NCH; ++c) {
        const int s = c & 1;
        if (c + 1 < NCH) {
            load_chunk(c + 1, (c + 1) & 1);
            asm volatile("cp.async.wait_group 1;" ::: "memory");
        } else {
            asm volatile("cp.async.wait_group 0;" ::: "memory");
        }
        __syncthreads();

        const float* as = As + s * GEMM_STAGE;
        const float* bs = Bs + s * GEMM_STAGE;
#pragma unroll
        for (int ks = 0; ks < 4; ++ks) {
            const int k0 = ks * 8;
            uint32_t af[4][4];
#pragma unroll
            for (int mt = 0; mt < 4; ++mt) {
                const int r = wm * 64 + mt * 16 + qr;
                af[mt][0] = rn_tf32_bits(as[(r    ) * LDP + k0     + qc]);
                af[mt][1] = rn_tf32_bits(as[(r + 8) * LDP + k0     + qc]);
                af[mt][2] = rn_tf32_bits(as[(r    ) * LDP + k0 + 4 + qc]);
                af[mt][3] = rn_tf32_bits(as[(r + 8) * LDP + k0 + 4 + qc]);
            }
            uint32_t bf[4][2];
#pragma unroll
            for (int nt = 0; nt < 4; ++nt) {
                const int rn = wn * 32 + nt * 8 + qr;
                bf[nt][0] = __float_as_uint(bs[rn * LDP + k0     + qc]);
                bf[nt][1] = __float_as_uint(bs[rn * LDP + k0 + 4 + qc]);
            }
#pragma unroll
            for (int mt = 0; mt < 4; ++mt)
#pragma unroll
                for (int nt = 0; nt < 4; ++nt)
                    mma_tf32(acc[mt][nt], af[mt], bf[nt]);
        }
        __syncthreads();
    }

#pragma unroll
    for (int mt = 0; mt < 4; ++mt) {
        const int row = m0 + wm * 64 + mt * 16 + qr;
#pragma unroll
        for (int nt = 0; nt < 4; ++nt) {
            const int col = n0 + wn * 32 + nt * 8 + 2 * qc;
            const float2 bv = *(const float2*)&bias[col];
            float2 o0, o1;
            o0.x = acc[mt][nt][0] + bv.x; o0.y = acc[mt][nt][1] + bv.y;
            o1.x = acc[mt][nt][2] + bv.x; o1.y = acc[mt][nt][3] + bv.y;
            *(float2*)&C[(size_t)row * N + col]       = o0;
            *(float2*)&C[(size_t)(row + 8) * N + col] = o1;
        }
    }
}

// ============================================================================
// Transpose + tf32 rounding: dst[Ccols][R] = rn(src[R][Ccols])
// ============================================================================
__global__ void __launch_bounds__(256) transpose_rn(
    const float* __restrict__ src, float* __restrict__ dst, int R, int Ccols)
{
    __shared__ float t[32][33];
    const int tx = threadIdx.x & 31;
    const int ty = threadIdx.x >> 5;
    const int c0 = blockIdx.x * 32;
    const int r0 = blockIdx.y * 32;
#pragma unroll
    for (int j = 0; j < 4; ++j)
        t[ty + 8 * j][tx] = src[(size_t)(r0 + ty + 8 * j) * Ccols + c0 + tx];
    __syncthreads();
#pragma unroll
    for (int j = 0; j < 4; ++j)
        dst[(size_t)(c0 + ty + 8 * j) * R + r0 + tx] = rn_tf32(t[tx][ty + 8 * j]);
}

// ============================================================================
// V transpose per head: g_v [BH, S, D] -> g_vt [BH, D, S] (tf32-rounded)
// ============================================================================
__global__ void __launch_bounds__(256) transpose_v_rn()
{
    __shared__ float t[32][33];
    const int tx = threadIdx.x & 31;
    const int ty = threadIdx.x >> 5;
    const int d0 = blockIdx.x * 32;
    const int s0 = blockIdx.y * 32;
    const int bh = blockIdx.z;
    const float* src = g_v + (size_t)bh * SEQ * HEAD_SIZE;
    float* dst = g_vt + (size_t)bh * HEAD_SIZE * SEQ;
#pragma unroll
    for (int j = 0; j < 4; ++j)
        t[ty + 8 * j][tx] = src[(size_t)(s0 + ty + 8 * j) * HEAD_SIZE + d0 + tx];
    __syncthreads();
#pragma unroll
    for (int j = 0; j < 4; ++j)
        dst[(size_t)(d0 + ty + 8 * j) * SEQ + s0 + tx] = rn_tf32(t[tx][ty + 8 * j]);
}

// ============================================================================
// rotary embedding + split into Q/K/V [B,H,S,D]
// ============================================================================
__global__ void __launch_bounds__(256) rope_split(
    const float* __restrict__ cosb, const float* __restrict__ sinb)
{
    const int t = blockIdx.x;
    const int b = t >> 10;
    const int s = t & 1023;
    const float* qkv = g_qkv + (size_t)t * QKV_N;

    for (int idx = threadIdx.x; idx < HIDDEN; idx += blockDim.x) {
        const int h = idx >> 7;
        const int d = idx & 127;
        const size_t src = (size_t)h * HEAD_SIZE + d;
        const size_t dst = ((size_t)(b * NUM_HEADS + h) * SEQ + s) * HEAD_SIZE + d;

        float qv = qkv[src];
        float kv = qkv[src + HIDDEN];
        float vv = qkv[src + 2 * HIDDEN];

        if (d < 2 * ROT) {
            if (d < ROT) {
                const float c  = cosb[t * ROT + d];
                const float sn = sinb[t * ROT + d];
                const float q2 = qkv[src + ROT];
                const float k2 = qkv[src + HIDDEN + ROT];
                qv = qv * c - q2 * sn;
                kv = kv * c - k2 * sn;
            } else {
                const int r = d - ROT;
                const float c  = cosb[t * ROT + r];
                const float sn = sinb[t * ROT + r];
                const float q1 = qkv[src - ROT];
                const float k1 = qkv[src + HIDDEN - ROT];
                qv = q1 * sn + qv * c;
                kv = k1 * sn + kv * c;
            }
        }
        g_q[dst] = qv;
        g_k[dst] = kv;
        g_v[dst] = vv;
    }
}

// ============================================================================
// flash attention v3 — tensor-core score AND PV (tf32 mma.sync).
// Block 256 thr = 8 warps. Q/K tiles 64x128 (tf32 in SMEM), Vt tile 128x64.
// Score: warp (wm=wid&3 rows*16, wn=wid>>2 cols*32), 16 ksteps x 4 MMAs.
// PV:    warp (rows wm*16, cols wn2=wid>>2 *64), 8 ksteps x 8 MMAs,
//        persistent acc[8][4] across kt with online-softmax rescaling.
// ============================================================================
#define FQT 64
#define FKT 64
#define LDT 132
#define LDSC 68
#define LDV 68

struct FlashSmem {
    float Qs[FQT][LDT];       // tf32, pre-scaled
    float Ks[FKT][LDT];       // tf32
    float Vt[HEAD_SIZE][LDV]; // tf32, [d][s]
    float Sc[FQT][LDSC];      // scores, then probs (tf32)
    float m_s[FQT];
    float l_s[FQT];
    float a_s[FQT];
};

__global__ void __launch_bounds__(256) flash_v3()
{
    extern __shared__ char sraw[];
    FlashSmem& S = *reinterpret_cast<FlashSmem*>(sraw);

    const int qt = blockIdx.x;
    const int h  = blockIdx.y;
    const int b  = blockIdx.z;
    const int tid  = threadIdx.x;
    const int wid  = tid >> 5;
    const int lane = tid & 31;
    const int qr = lane >> 2;
    const int qc = lane & 3;
    const int wm = wid & 3;           // row band (16 rows) for score & PV
    const int wn = wid >> 2;          // score: col band*32 ; PV: col band*64
    const int bh = b * NUM_HEADS + h;
    const size_t headbase = (size_t)bh * SEQ * HEAD_SIZE;
    const float scale = 0.08838834764831845f;   // 1/sqrt(128)

    // ---- load Q tile: scale + tf32 round ----
    {
        const float* qg = g_q + headbase + (size_t)(qt * FQT) * HEAD_SIZE;
#pragma unroll
        for (int it = 0; it < 8; ++it) {
            const int flat = it * 256 + tid;
            const int r = flat >> 5;
            const int d4 = (flat & 31) << 2;
            float4 v = *(const float4*)(qg + (size_t)r * HEAD_SIZE + d4);
            v.x = rn_tf32(v.x * scale); v.y = rn_tf32(v.y * scale);
            v.z = rn_tf32(v.z * scale); v.w = rn_tf32(v.w * scale);
            *(float4*)&S.Qs[r][d4] = v;
        }
    }
    if (tid < FQT) { S.m_s[tid] = -1e30f; S.l_s[tid] = 0.0f; }

    // persistent PV accumulator: rows wm*16+qr(+8), cols wn*64 + nt*8 + 2qc(+1)
    float oacc[8][4];
#pragma unroll
    for (int i = 0; i < 8; ++i)
#pragma unroll
        for (int j = 0; j < 4; ++j) oacc[i][j] = 0.0f;

    const int nkt = qt + 1;
    for (int kt = 0; kt < nkt; ++kt) {
        __syncthreads();   // prior iteration fully done before tile overwrite
        // ---- load K tile (round) + Vt tile (pre-rounded) ----
        {
            const float* kg = g_k + headbase + (size_t)(kt * FKT) * HEAD_SIZE;
#pragma unroll
            for (int it = 0; it < 8; ++it) {
                const int flat = it * 256 + tid;
                const int r = flat >> 5;
                const int d4 = (flat & 31) << 2;
                float4 v = *(const float4*)(kg + (size_t)r * HEAD_SIZE + d4);
                v.x = rn_tf32(v.x); v.y = rn_tf32(v.y);
                v.z = rn_tf32(v.z); v.w = rn_tf32(v.w);
                *(float4*)&S.Ks[r][d4] = v;
            }
            const float* vg = g_vt + (size_t)bh * HEAD_SIZE * SEQ + kt * FKT;
#pragma unroll
            for (int it = 0; it < 8; ++it) {
                const int flat = it * 256 + tid;      // 128 rows x 16 float4
                const int d = flat >> 4;
                const int s4 = (flat & 15) << 2;
                *(float4*)&S.Vt[d][s4] = *(const float4*)(vg + (size_t)d * SEQ + s4);
            }
        }
        __syncthreads();

        // ---- score: S[64x64] = Qs @ Ks^T via mma (warp tile 16x32) ----
        {
            float sacc[4][4];
#pragma unroll
            for (int i = 0; i < 4; ++i)
#pragma unroll
                for (int j = 0; j < 4; ++j) sacc[i][j] = 0.0f;
            const int m0 = wm * 16;
            const int n0 = wn * 32;
#pragma unroll
            for (int ks = 0; ks < 16; ++ks) {
                const int k0 = ks * 8;
                uint32_t af[4];
                af[0] = __float_as_uint(S.Qs[m0 + qr    ][k0 + qc]);
                af[1] = __float_as_uint(S.Qs[m0 + qr + 8][k0 + qc]);
                af[2] = __float_as_uint(S.Qs[m0 + qr    ][k0 + qc + 4]);
                af[3] = __float_as_uint(S.Qs[m0 + qr + 8][k0 + qc + 4]);
#pragma unroll
                for (int nt = 0; nt < 4; ++nt) {
                    uint32_t bf[2];
                    const int n = n0 + nt * 8 + qr;
                    bf[0] = __float_as_uint(S.Ks[n][k0 + qc]);
                    bf[1] = __float_as_uint(S.Ks[n][k0 + qc + 4]);
                    mma_tf32(sacc[nt], af, bf);
                }
            }
#pragma unroll
            for (int nt = 0; nt < 4; ++nt) {
                const int col = n0 + nt * 8 + 2 * qc;
                *(float2*)&S.Sc[m0 + qr    ][col] = make_float2(sacc[nt][0], sacc[nt][1]);
                *(float2*)&S.Sc[m0 + qr + 8][col] = make_float2(sacc[nt][2], sacc[nt][3]);
            }
        }
        __syncthreads();

        // ---- online softmax (4 threads per row); probs tf32-rounded ----
        {
            const int row = tid >> 2;
            const int sub = tid & 3;
            const int sq  = qt * FQT + row;
            const int c0  = sub * 16;
            float sv[16];
            float mx = -1e30f;
#pragma unroll
            for (int jj = 0; jj < 16; ++jj) {
                const int cg = kt * FKT + c0 + jj;
                float s = S.Sc[row][c0 + jj];
                s = (cg > sq) ? -1e30f : s;
                sv[jj] = s;
                mx = fmaxf(mx, s);
            }
            mx = fmaxf(mx, __shfl_xor_sync(0xffffffffu, mx, 1));
            mx = fmaxf(mx, __shfl_xor_sync(0xffffffffu, mx, 2));
            const float m_old = S.m_s[row];
            const float m_new = fmaxf(m_old, mx);
            float sum = 0.0f;
#pragma unroll
            for (int jj = 0; jj < 16; ++jj) {
                const float p = __expf(sv[jj] - m_new);
                S.Sc[row][c0 + jj] = rn_tf32(p);
                sum += p;
            }
            sum += __shfl_xor_sync(0xffffffffu, sum, 1);
            sum += __shfl_xor_sync(0xffffffffu, sum, 2);
            __syncwarp();
            if (sub == 0) {
                const float alpha = __expf(m_old - m_new);
                S.a_s[row] = alpha;
                S.m_s[row] = m_new;
                S.l_s[row] = S.l_s[row] * alpha + sum;
            }
        }
        __syncthreads();

        // ---- PV: O += P @ V via mma (warp tile 16x64 over d) ----
        {
            const int m0 = wm * 16;
            const int n0 = wn * 64;
            const float al0 = S.a_s[m0 + qr];
            const float al1 = S.a_s[m0 + qr + 8];
#pragma unroll
            for (int nt = 0; nt < 8; ++nt) {
                oacc[nt][0] *= al0; oacc[nt][1] *= al0;
                oacc[nt][2] *= al1; oacc[nt][3] *= al1;
            }
#pragma unroll
            for (int ks = 0; ks < 8; ++ks) {
                const int k0 = ks * 8;
                uint32_t af[4];
                af[0] = __float_as_uint(S.Sc[m0 + qr    ][k0 + qc]);
                af[1] = __float_as_uint(S.Sc[m0 + qr + 8][k0 + qc]);
                af[2] = __float_as_uint(S.Sc[m0 + qr    ][k0 + qc + 4]);
                af[3] = __float_as_uint(S.Sc[m0 + qr + 8][k0 + qc + 4]);
#pragma unroll
                for (int nt = 0; nt < 8; ++nt) {
                    uint32_t bf[2];
                    const int n = n0 + nt * 8 + qr;     // d dimension
                    bf[0] = __float_as_uint(S.Vt[n][k0 + qc]);
                    bf[1] = __float_as_uint(S.Vt[n][k0 + qc + 4]);
                    mma_tf32(oacc[nt], af, bf);
                }
            }
        }
    }

    // ---- epilogue: normalize, tf32-round (feeds tf32 dense GEMM), store ----
    {
        const int m0 = wm * 16;
        const int n0 = wn * 64;
        const int t0 = b * SEQ + qt * FQT;
        const float inv0 = 1.0f / S.l_s[m0 + qr];
        const float inv1 = 1.0f / S.l_s[m0 + qr + 8];
#pragma unroll
        for (int nt = 0; nt < 8; ++nt) {
            const int col = h * HEAD_SIZE + n0 + nt * 8 + 2 * qc;
            float2 o0, o1;
            o0.x = rn_tf32(oacc[nt][0] * inv0); o0.y = rn_tf32(oacc[nt][1] * inv0);
            o1.x = rn_tf32(oacc[nt][2] * inv1); o1.y = rn_tf32(oacc[nt][3] * inv1);
            *(float2*)&g_attn[(size_t)(t0 + m0 + qr    ) * HIDDEN + col] = o0;
            *(float2*)&g_attn[(size_t)(t0 + m0 + qr + 8) * HIDDEN + col] = o1;
        }
    }
}

// ============================================================================
// launch
// ============================================================================
extern "C" void kernel_launch(void* const* d_in, const int* in_sizes, int n_in,
                              void* d_out, int out_size)
{
    const float* hidden  = (const float*)d_in[0];
    const float* cosb    = (const float*)d_in[1];
    const float* sinb    = (const float*)d_in[2];
    const float* W_qkv   = (const float*)d_in[3];
    const float* b_qkv   = (const float*)d_in[4];
    const float* W_dense = (const float*)d_in[5];
    const float* b_dense = (const float*)d_in[6];
    float* out = (float*)d_out;

    float *qkv_ptr, *attn_ptr, *wqkvT_ptr, *wdenseT_ptr;
    cudaGetSymbolAddress((void**)&qkv_ptr, g_qkv);
    cudaGetSymbolAddress((void**)&attn_ptr, g_attn);
    cudaGetSymbolAddress((void**)&wqkvT_ptr, g_wqkvT);
    cudaGetSymbolAddress((void**)&wdenseT_ptr, g_wdenseT);

    cudaFuncSetAttribute(flash_v3, cudaFuncAttributeMaxDynamicSharedMemorySize,
                         (int)sizeof(FlashSmem));
    cudaFuncSetAttribute(gemm_tf32_mma, cudaFuncAttributeMaxDynamicSharedMemorySize,
                         GEMM_SMEM_BYTES);

    // 0) weight prep: transpose + tf32 rounding (B operands)
    transpose_rn<<<dim3(QKV_N / 32, HIDDEN / 32), 256>>>(W_qkv, wqkvT_ptr, HIDDEN, QKV_N);
    transpose_rn<<<dim3(HIDDEN / 32, HIDDEN / 32), 256>>>(W_dense, wdenseT_ptr, HIDDEN, HIDDEN);

    // 1) QKV projection (tf32 mma.sync)
    gemm_tf32_mma<<<dim3(QKV_N / 128, TOTAL / 128), 256, GEMM_SMEM_BYTES>>>(
        hidden, wqkvT_ptr, b_qkv, qkv_ptr, TOTAL, QKV_N, HIDDEN);
    // 2) rotary + split
    rope_split<<<TOTAL, 256>>>(cosb, sinb);
    // 2b) V transpose per head (tf32-rounded)
    transpose_v_rn<<<dim3(HEAD_SIZE / 32, SEQ / 32, BATCH * NUM_HEADS), 256>>>();
    // 3) causal flash attention (tensor-core score + PV)
    flash_v3<<<dim3(SEQ / FQT, NUM_HEADS, BATCH), 256, sizeof(FlashSmem)>>>();
    // 4) dense projection (tf32 mma.sync)
    gemm_tf32_mma<<<dim3(HIDDEN / 128, TOTAL / 128), 256, GEMM_SMEM_BYTES>>>(
        attn_ptr, wdenseT_ptr, b_dense, out, TOTAL, HIDDEN, HIDDEN);
}

// round 7
// speedup vs baseline: 5.1491x; 1.4412x over previous
#include <cuda_runtime.h>
#include <cuda.h>
#include <cuda_fp16.h>
#include <math.h>
#include <stdint.h>

// Problem constants
#define NUM_HEADS 16
#define HEAD_SIZE 128
#define HIDDEN    2048
#define ROT       16
#define BATCH     4
#define SEQ       1024
#define TOTAL     4096
#define QKV_N     6144

// -------- device scratch --------
__device__ float  g_qkv[(size_t)TOTAL * QKV_N];
__device__ float  g_q[(size_t)TOTAL * HIDDEN];
__device__ float  g_k[(size_t)TOTAL * HIDDEN];
__device__ float  g_v[(size_t)TOTAL * HIDDEN];
__device__ float  g_vt[(size_t)BATCH * NUM_HEADS * HEAD_SIZE * SEQ];  // [B,H,D,S] tf32
__device__ __half g_attnh[(size_t)TOTAL * HIDDEN];     // flash output (half)
__device__ __half g_hidh[(size_t)TOTAL * HIDDEN];      // hidden states (half)
__device__ __half g_wqkvTh[(size_t)QKV_N * HIDDEN];    // W_qkv^T [N][K] half
__device__ __half g_wdenseTh[(size_t)HIDDEN * HIDDEN]; // W_dense^T [N][K] half

// ============================================================================
// helpers
// ============================================================================
__device__ __forceinline__ uint32_t smem_u32(const void* p) {
    uint32_t a;
    asm("{ .reg .u64 t; cvta.to.shared.u64 t, %1; cvt.u32.u64 %0, t; }" : "=r"(a) : "l"(p));
    return a;
}
__device__ __forceinline__ float rn_tf32(float x) {
    uint32_t b;
    asm("cvt.rna.tf32.f32 %0, %1;" : "=r"(b) : "f"(x));
    return __uint_as_float(b);
}
__device__ __forceinline__ void mma_tf32(float* c, const uint32_t* a, const uint32_t* b) {
    asm volatile(
        "mma.sync.aligned.m16n8k8.row.col.f32.tf32.tf32.f32 "
        "{%0,%1,%2,%3}, {%4,%5,%6,%7}, {%8,%9}, {%0,%1,%2,%3};"
        : "+f"(c[0]), "+f"(c[1]), "+f"(c[2]), "+f"(c[3])
        : "r"(a[0]), "r"(a[1]), "r"(a[2]), "r"(a[3]), "r"(b[0]), "r"(b[1]));
}
__device__ __forceinline__ void mma_f16(float* c, const uint32_t* a, uint32_t b0, uint32_t b1) {
    asm volatile(
        "mma.sync.aligned.m16n8k16.row.col.f32.f16.f16.f32 "
        "{%0,%1,%2,%3}, {%4,%5,%6,%7}, {%8,%9}, {%0,%1,%2,%3};"
        : "+f"(c[0]), "+f"(c[1]), "+f"(c[2]), "+f"(c[3])
        : "r"(a[0]), "r"(a[1]), "r"(a[2]), "r"(a[3]), "r"(b0), "r"(b1));
}
__device__ __forceinline__ void ldsm_x4(uint32_t* r, uint32_t addr) {
    asm volatile("ldmatrix.sync.aligned.m8n8.x4.shared.b16 {%0,%1,%2,%3}, [%4];"
        : "=r"(r[0]), "=r"(r[1]), "=r"(r[2]), "=r"(r[3]) : "r"(addr));
}

// ============================================================================
// fp16 mma.sync GEMM: C[M,N] = A[M,K] @ Bt[N,K]^T + bias (fp32 accum/output)
// 128x128 CTA tile, 8 warps (2x4), warp tile 64x32, K-chunk 64, double-buffer,
// ldmatrix fragment loads.
// ============================================================================
#define KCH 64
#define LDH 72                           // halves per smem row (144B: LDSM conflict-free)
#define GEMM_STAGE (128 * LDH)           // halves per stage per matrix
#define GEMM_SMEM_BYTES (2 * GEMM_STAGE * 2 * 2)    // 73728 B

__global__ void __launch_bounds__(256, 2) gemm_f16_mma(
    const __half* __restrict__ A, const __half* __restrict__ Bt,
    const float* __restrict__ bias, float* __restrict__ C,
    int M, int N, int K)
{
    extern __shared__ __half hsm[];
    __half* As = hsm;                       // [2][128][LDH]
    __half* Bs = hsm + 2 * GEMM_STAGE;      // [2][128][LDH]

    const int tid  = threadIdx.x;
    const int wid  = tid >> 5;
    const int lane = tid & 31;
    const int wm = wid >> 2;          // 0..1
    const int wn = wid & 3;           // 0..3
    const int qr = lane >> 2;         // 0..7
    const int qc = lane & 3;          // 0..3
    const int m0 = blockIdx.y * 128;
    const int n0 = blockIdx.x * 128;

    // ldmatrix lane addressing: row = base + (lane&15), col = k0 + (lane>>4)*8
    const int lrow = lane & 15;
    const int lcol = (lane >> 4) * 8;

    float acc[4][4][4];
#pragma unroll
    for (int i = 0; i < 4; ++i)
#pragma unroll
        for (int j = 0; j < 4; ++j)
#pragma unroll
            for (int k = 0; k < 4; ++k) acc[i][j][k] = 0.0f;

    auto load_chunk = [&](int c, int s) {
        const int kbase = c * KCH;
#pragma unroll
        for (int it = 0; it < 4; ++it) {
            const int idx = it * 256 + tid;   // 0..1023 (16B ops per matrix)
            const int row = idx >> 3;         // 0..127
            const int c8  = (idx & 7) << 3;   // 0..56 halves
            const __half* srcA = A  + (size_t)(m0 + row) * K + kbase + c8;
            const __half* srcB = Bt + (size_t)(n0 + row) * K + kbase + c8;
            const uint32_t da = smem_u32(&As[s * GEMM_STAGE + row * LDH + c8]);
            const uint32_t db = smem_u32(&Bs[s * GEMM_STAGE + row * LDH + c8]);
            asm volatile("cp.async.cg.shared.global [%0], [%1], 16;" :: "r"(da), "l"(srcA) : "memory");
            asm volatile("cp.async.cg.shared.global [%0], [%1], 16;" :: "r"(db), "l"(srcB) : "memory");
        }
        asm volatile("cp.async.commit_group;" ::: "memory");
    };

    const int NCH = K / KCH;
    load_chunk(0, 0);

    for (int c = 0; c < NCH; ++c) {
        const int s = c & 1;
        if (c + 1 < NCH) {
            load_chunk(c + 1, (c + 1) & 1);
            asm volatile("cp.async.wait_group 1;" ::: "memory");
        } else {
            asm volatile("cp.async.wait_group 0;" ::: "memory");
        }
        __syncthreads();

        const __half* as = As + s * GEMM_STAGE;
        const __half* bs = Bs + s * GEMM_STAGE;
#pragma unroll
        for (int ks = 0; ks < 4; ++ks) {
            const int k0 = ks * 16;
            uint32_t af[4][4];
#pragma unroll
            for (int mt = 0; mt < 4; ++mt)
                ldsm_x4(af[mt], smem_u32(&as[(wm * 64 + mt * 16 + lrow) * LDH + k0 + lcol]));
            uint32_t bf[2][4];
#pragma unroll
            for (int nt2 = 0; nt2 < 2; ++nt2)
                ldsm_x4(bf[nt2], smem_u32(&bs[(wn * 32 + nt2 * 16 + lrow) * LDH + k0 + lcol]));
#pragma unroll
            for (int mt = 0; mt < 4; ++mt)
#pragma unroll
                for (int nt = 0; nt < 4; ++nt)
                    mma_f16(acc[mt][nt], af[mt], bf[nt >> 1][nt & 1], bf[nt >> 1][2 + (nt & 1)]);
        }
        __syncthreads();
    }

#pragma unroll
    for (int mt = 0; mt < 4; ++mt) {
        const int row = m0 + wm * 64 + mt * 16 + qr;
#pragma unroll
        for (int nt = 0; nt < 4; ++nt) {
            const int col = n0 + wn * 32 + nt * 8 + 2 * qc;
            const float2 bv = *(const float2*)&bias[col];
            float2 o0, o1;
            o0.x = acc[mt][nt][0] + bv.x; o0.y = acc[mt][nt][1] + bv.y;
            o1.x = acc[mt][nt][2] + bv.x; o1.y = acc[mt][nt][3] + bv.y;
            *(float2*)&C[(size_t)row * N + col]       = o0;
            *(float2*)&C[(size_t)(row + 8) * N + col] = o1;
        }
    }
}

// ============================================================================
// float -> half bulk convert
// ============================================================================
__global__ void __launch_bounds__(256) f2h_copy(
    const float* __restrict__ src, __half* __restrict__ dst, int n4)
{
    const int i = blockIdx.x * 256 + threadIdx.x;
    if (i < n4) {
        float4 v = ((const float4*)src)[i];
        ((__half2*)dst)[2 * i]     = __floats2half2_rn(v.x, v.y);
        ((__half2*)dst)[2 * i + 1] = __floats2half2_rn(v.z, v.w);
    }
}

// ============================================================================
// Transpose + half convert: dst[Ccols][R] = h(src[R][Ccols])
// ============================================================================
__global__ void __launch_bounds__(256) transpose_h(
    const float* __restrict__ src, __half* __restrict__ dst, int R, int Ccols)
{
    __shared__ float t[32][33];
    const int tx = threadIdx.x & 31;
    const int ty = threadIdx.x >> 5;
    const int c0 = blockIdx.x * 32;
    const int r0 = blockIdx.y * 32;
#pragma unroll
    for (int j = 0; j < 4; ++j)
        t[ty + 8 * j][tx] = src[(size_t)(r0 + ty + 8 * j) * Ccols + c0 + tx];
    __syncthreads();
#pragma unroll
    for (int j = 0; j < 4; ++j)
        dst[(size_t)(c0 + ty + 8 * j) * R + r0 + tx] = __float2half_rn(t[tx][ty + 8 * j]);
}

// ============================================================================
// V transpose per head: g_v [BH, S, D] -> g_vt [BH, D, S] (tf32-rounded)
// ============================================================================
__global__ void __launch_bounds__(256) transpose_v_rn()
{
    __shared__ float t[32][33];
    const int tx = threadIdx.x & 31;
    const int ty = threadIdx.x >> 5;
    const int d0 = blockIdx.x * 32;
    const int s0 = blockIdx.y * 32;
    const int bh = blockIdx.z;
    const float* src = g_v + (size_t)bh * SEQ * HEAD_SIZE;
    float* dst = g_vt + (size_t)bh * HEAD_SIZE * SEQ;
#pragma unroll
    for (int j = 0; j < 4; ++j)
        t[ty + 8 * j][tx] = src[(size_t)(s0 + ty + 8 * j) * HEAD_SIZE + d0 + tx];
    __syncthreads();
#pragma unroll
    for (int j = 0; j < 4; ++j)
        dst[(size_t)(d0 + ty + 8 * j) * SEQ + s0 + tx] = rn_tf32(t[tx][ty + 8 * j]);
}

// ============================================================================
// rotary embedding + split into Q/K/V [B,H,S,D]
// ============================================================================
__global__ void __launch_bounds__(256) rope_split(
    const float* __restrict__ cosb, const float* __restrict__ sinb)
{
    const int t = blockIdx.x;
    const int b = t >> 10;
    const int s = t & 1023;
    const float* qkv = g_qkv + (size_t)t * QKV_N;

    for (int idx = threadIdx.x; idx < HIDDEN; idx += blockDim.x) {
        const int h = idx >> 7;
        const int d = idx & 127;
        const size_t src = (size_t)h * HEAD_SIZE + d;
        const size_t dst = ((size_t)(b * NUM_HEADS + h) * SEQ + s) * HEAD_SIZE + d;

        float qv = qkv[src];
        float kv = qkv[src + HIDDEN];
        float vv = qkv[src + 2 * HIDDEN];

        if (d < 2 * ROT) {
            if (d < ROT) {
                const float c  = cosb[t * ROT + d];
                const float sn = sinb[t * ROT + d];
                const float q2 = qkv[src + ROT];
                const float k2 = qkv[src + HIDDEN + ROT];
                qv = qv * c - q2 * sn;
                kv = kv * c - k2 * sn;
            } else {
                const int r = d - ROT;
                const float c  = cosb[t * ROT + r];
                const float sn = sinb[t * ROT + r];
                const float q1 = qkv[src - ROT];
                const float k1 = qkv[src + HIDDEN - ROT];
                qv = q1 * sn + qv * c;
                kv = k1 * sn + kv * c;
            }
        }
        g_q[dst] = qv;
        g_k[dst] = kv;
        g_v[dst] = vv;
    }
}

// ============================================================================
// flash attention v3 — tensor-core score AND PV (tf32 mma.sync).
// Epilogue writes half (feeds fp16 dense GEMM).
// ============================================================================
#define FQT 64
#define FKT 64
#define LDT 132
#define LDSC 68
#define LDV 68

struct FlashSmem {
    float Qs[FQT][LDT];
    float Ks[FKT][LDT];
    float Vt[HEAD_SIZE][LDV];
    float Sc[FQT][LDSC];
    float m_s[FQT];
    float l_s[FQT];
    float a_s[FQT];
};

__global__ void __launch_bounds__(256) flash_v3()
{
    extern __shared__ char sraw[];
    FlashSmem& S = *reinterpret_cast<FlashSmem*>(sraw);

    const int qt = blockIdx.x;
    const int h  = blockIdx.y;
    const int b  = blockIdx.z;
    const int tid  = threadIdx.x;
    const int wid  = tid >> 5;
    const int lane = tid & 31;
    const int qr = lane >> 2;
    const int qc = lane & 3;
    const int wm = wid & 3;
    const int wn = wid >> 2;
    const int bh = b * NUM_HEADS + h;
    const size_t headbase = (size_t)bh * SEQ * HEAD_SIZE;
    const float scale = 0.08838834764831845f;

    {
        const float* qg = g_q + headbase + (size_t)(qt * FQT) * HEAD_SIZE;
#pragma unroll
        for (int it = 0; it < 8; ++it) {
            const int flat = it * 256 + tid;
            const int r = flat >> 5;
            const int d4 = (flat & 31) << 2;
            float4 v = *(const float4*)(qg + (size_t)r * HEAD_SIZE + d4);
            v.x = rn_tf32(v.x * scale); v.y = rn_tf32(v.y * scale);
            v.z = rn_tf32(v.z * scale); v.w = rn_tf32(v.w * scale);
            *(float4*)&S.Qs[r][d4] = v;
        }
    }
    if (tid < FQT) { S.m_s[tid] = -1e30f; S.l_s[tid] = 0.0f; }

    float oacc[8][4];
#pragma unroll
    for (int i = 0; i < 8; ++i)
#pragma unroll
        for (int j = 0; j < 4; ++j) oacc[i][j] = 0.0f;

    const int nkt = qt + 1;
    for (int kt = 0; kt < nkt; ++kt) {
        __syncthreads();
        {
            const float* kg = g_k + headbase + (size_t)(kt * FKT) * HEAD_SIZE;
#pragma unroll
            for (int it = 0; it < 8; ++it) {
                const int flat = it * 256 + tid;
                const int r = flat >> 5;
                const int d4 = (flat & 31) << 2;
                float4 v = *(const float4*)(kg + (size_t)r * HEAD_SIZE + d4);
                v.x = rn_tf32(v.x); v.y = rn_tf32(v.y);
                v.z = rn_tf32(v.z); v.w = rn_tf32(v.w);
                *(float4*)&S.Ks[r][d4] = v;
            }
            const float* vg = g_vt + (size_t)bh * HEAD_SIZE * SEQ + kt * FKT;
#pragma unroll
            for (int it = 0; it < 8; ++it) {
                const int flat = it * 256 + tid;
                const int d = flat >> 4;
                const int s4 = (flat & 15) << 2;
                *(float4*)&S.Vt[d][s4] = *(const float4*)(vg + (size_t)d * SEQ + s4);
            }
        }
        __syncthreads();

        // score
        {
            float sacc[4][4];
#pragma unroll
            for (int i = 0; i < 4; ++i)
#pragma unroll
                for (int j = 0; j < 4; ++j) sacc[i][j] = 0.0f;
            const int m0 = wm * 16;
            const int n0 = wn * 32;
#pragma unroll
            for (int ks = 0; ks < 16; ++ks) {
                const int k0 = ks * 8;
                uint32_t af[4];
                af[0] = __float_as_uint(S.Qs[m0 + qr    ][k0 + qc]);
                af[1] = __float_as_uint(S.Qs[m0 + qr + 8][k0 + qc]);
                af[2] = __float_as_uint(S.Qs[m0 + qr    ][k0 + qc + 4]);
                af[3] = __float_as_uint(S.Qs[m0 + qr + 8][k0 + qc + 4]);
#pragma unroll
                for (int nt = 0; nt < 4; ++nt) {
                    uint32_t bf[2];
                    const int n = n0 + nt * 8 + qr;
                    bf[0] = __float_as_uint(S.Ks[n][k0 + qc]);
                    bf[1] = __float_as_uint(S.Ks[n][k0 + qc + 4]);
                    mma_tf32(sacc[nt], af, bf);
                }
            }
#pragma unroll
            for (int nt = 0; nt < 4; ++nt) {
                const int col = n0 + nt * 8 + 2 * qc;
                *(float2*)&S.Sc[m0 + qr    ][col] = make_float2(sacc[nt][0], sacc[nt][1]);
                *(float2*)&S.Sc[m0 + qr + 8][col] = make_float2(sacc[nt][2], sacc[nt][3]);
            }
        }
        __syncthreads();

        // online softmax
        {
            const int row = tid >> 2;
            const int sub = tid & 3;
            const int sq  = qt * FQT + row;
            const int c0  = sub * 16;
            float sv[16];
            float mx = -1e30f;
#pragma unroll
            for (int jj = 0; jj < 16; ++jj) {
                const int cg = kt * FKT + c0 + jj;
                float s = S.Sc[row][c0 + jj];
                s = (cg > sq) ? -1e30f : s;
                sv[jj] = s;
                mx = fmaxf(mx, s);
            }
            mx = fmaxf(mx, __shfl_xor_sync(0xffffffffu, mx, 1));
            mx = fmaxf(mx, __shfl_xor_sync(0xffffffffu, mx, 2));
            const float m_old = S.m_s[row];
            const float m_new = fmaxf(m_old, mx);
            float sum = 0.0f;
#pragma unroll
            for (int jj = 0; jj < 16; ++jj) {
                const float p = __expf(sv[jj] - m_new);
                S.Sc[row][c0 + jj] = rn_tf32(p);
                sum += p;
            }
            sum += __shfl_xor_sync(0xffffffffu, sum, 1);
            sum += __shfl_xor_sync(0xffffffffu, sum, 2);
            __syncwarp();
            if (sub == 0) {
                const float alpha = __expf(m_old - m_new);
                S.a_s[row] = alpha;
                S.m_s[row] = m_new;
                S.l_s[row] = S.l_s[row] * alpha + sum;
            }
        }
        __syncthreads();

        // PV
        {
            const int m0 = wm * 16;
            const int n0 = wn * 64;
            const float al0 = S.a_s[m0 + qr];
            const float al1 = S.a_s[m0 + qr + 8];
#pragma unroll
            for (int nt = 0; nt < 8; ++nt) {
                oacc[nt][0] *= al0; oacc[nt][1] *= al0;
                oacc[nt][2] *= al1; oacc[nt][3] *= al1;
            }
#pragma unroll
            for (int ks = 0; ks < 8; ++ks) {
                const int k0 = ks * 8;
                uint32_t af[4];
                af[0] = __float_as_uint(S.Sc[m0 + qr    ][k0 + qc]);
                af[1] = __float_as_uint(S.Sc[m0 + qr + 8][k0 + qc]);
                af[2] = __float_as_uint(S.Sc[m0 + qr    ][k0 + qc + 4]);
                af[3] = __float_as_uint(S.Sc[m0 + qr + 8][k0 + qc + 4]);
#pragma unroll
                for (int nt = 0; nt < 8; ++nt) {
                    uint32_t bf[2];
                    const int n = n0 + nt * 8 + qr;
                    bf[0] = __float_as_uint(S.Vt[n][k0 + qc]);
                    bf[1] = __float_as_uint(S.Vt[n][k0 + qc + 4]);
                    mma_tf32(oacc[nt], af, bf);
                }
            }
        }
    }

    // epilogue: normalize, store as half for the fp16 dense GEMM
    {
        const int m0 = wm * 16;
        const int n0 = wn * 64;
        const int t0 = b * SEQ + qt * FQT;
        const float inv0 = 1.0f / S.l_s[m0 + qr];
        const float inv1 = 1.0f / S.l_s[m0 + qr + 8];
#pragma unroll
        for (int nt = 0; nt < 8; ++nt) {
            const int col = h * HEAD_SIZE + n0 + nt * 8 + 2 * qc;
            *(__half2*)&g_attnh[(size_t)(t0 + m0 + qr    ) * HIDDEN + col] =
                __floats2half2_rn(oacc[nt][0] * inv0, oacc[nt][1] * inv0);
            *(__half2*)&g_attnh[(size_t)(t0 + m0 + qr + 8) * HIDDEN + col] =
                __floats2half2_rn(oacc[nt][2] * inv1, oacc[nt][3] * inv1);
        }
    }
}

// ============================================================================
// launch
// ============================================================================
extern "C" void kernel_launch(void* const* d_in, const int* in_sizes, int n_in,
                              void* d_out, int out_size)
{
    const float* hidden  = (const float*)d_in[0];
    const float* cosb    = (const float*)d_in[1];
    const float* sinb    = (const float*)d_in[2];
    const float* W_qkv   = (const float*)d_in[3];
    const float* b_qkv   = (const float*)d_in[4];
    const float* W_dense = (const float*)d_in[5];
    const float* b_dense = (const float*)d_in[6];
    float* out = (float*)d_out;

    float *qkv_ptr;
    __half *attnh_ptr, *hidh_ptr, *wqkvTh_ptr, *wdenseTh_ptr;
    cudaGetSymbolAddress((void**)&qkv_ptr, g_qkv);
    cudaGetSymbolAddress((void**)&attnh_ptr, g_attnh);
    cudaGetSymbolAddress((void**)&hidh_ptr, g_hidh);
    cudaGetSymbolAddress((void**)&wqkvTh_ptr, g_wqkvTh);
    cudaGetSymbolAddress((void**)&wdenseTh_ptr, g_wdenseTh);

    cudaFuncSetAttribute(flash_v3, cudaFuncAttributeMaxDynamicSharedMemorySize,
                         (int)sizeof(FlashSmem));
    cudaFuncSetAttribute(gemm_f16_mma, cudaFuncAttributeMaxDynamicSharedMemorySize,
                         GEMM_SMEM_BYTES);

    // 0) operand prep (half)
    {
        const int n4 = TOTAL * HIDDEN / 4;
        f2h_copy<<<(n4 + 255) / 256, 256>>>(hidden, hidh_ptr, n4);
        transpose_h<<<dim3(QKV_N / 32, HIDDEN / 32), 256>>>(W_qkv, wqkvTh_ptr, HIDDEN, QKV_N);
        transpose_h<<<dim3(HIDDEN / 32, HIDDEN / 32), 256>>>(W_dense, wdenseTh_ptr, HIDDEN, HIDDEN);
    }
    // 1) QKV projection (fp16 mma + ldmatrix)
    gemm_f16_mma<<<dim3(QKV_N / 128, TOTAL / 128), 256, GEMM_SMEM_BYTES>>>(
        hidh_ptr, wqkvTh_ptr, b_qkv, qkv_ptr, TOTAL, QKV_N, HIDDEN);
    // 2) rotary + split
    rope_split<<<TOTAL, 256>>>(cosb, sinb);
    // 2b) V transpose per head (tf32)
    transpose_v_rn<<<dim3(HEAD_SIZE / 32, SEQ / 32, BATCH * NUM_HEADS), 256>>>();
    // 3) causal flash attention (tensor-core, tf32)
    flash_v3<<<dim3(SEQ / FQT, NUM_HEADS, BATCH), 256, sizeof(FlashSmem)>>>();
    // 4) dense projection (fp16 mma + ldmatrix)
    gemm_f16_mma<<<dim3(HIDDEN / 128, TOTAL / 128), 256, GEMM_SMEM_BYTES>>>(
        attnh_ptr, wdenseTh_ptr, b_dense, out, TOTAL, HIDDEN, HIDDEN);
}

// round 8
// speedup vs baseline: 7.0252x; 1.3644x over previous
#include <cuda_runtime.h>
#include <cuda.h>
#include <cuda_fp16.h>
#include <math.h>
#include <stdint.h>

// Problem constants
#define NUM_HEADS 16
#define HEAD_SIZE 128
#define HIDDEN    2048
#define ROT       16
#define BATCH     4
#define SEQ       1024
#define TOTAL     4096
#define QKV_N     6144

// -------- device scratch --------
__device__ float  g_qkv[(size_t)TOTAL * QKV_N];
__device__ __half g_qh[(size_t)TOTAL * HIDDEN];        // Q half, pre-scaled, [B,H,S,D]
__device__ __half g_kh[(size_t)TOTAL * HIDDEN];        // K half, [B,H,S,D]
__device__ float  g_v[(size_t)TOTAL * HIDDEN];         // V fp32, [B,H,S,D]
__device__ __half g_vth[(size_t)BATCH * NUM_HEADS * HEAD_SIZE * SEQ];  // V^T half [B,H,D,S]
__device__ __half g_attnh[(size_t)TOTAL * HIDDEN];     // flash output (half)
__device__ __half g_hidh[(size_t)TOTAL * HIDDEN];      // hidden states (half)
__device__ __half g_wqkvTh[(size_t)QKV_N * HIDDEN];    // W_qkv^T [N][K] half
__device__ __half g_wdenseTh[(size_t)HIDDEN * HIDDEN]; // W_dense^T [N][K] half

// ============================================================================
// helpers
// ============================================================================
__device__ __forceinline__ uint32_t smem_u32(const void* p) {
    uint32_t a;
    asm("{ .reg .u64 t; cvta.to.shared.u64 t, %1; cvt.u32.u64 %0, t; }" : "=r"(a) : "l"(p));
    return a;
}
__device__ __forceinline__ void mma_f16(float* c, const uint32_t* a, uint32_t b0, uint32_t b1) {
    asm volatile(
        "mma.sync.aligned.m16n8k16.row.col.f32.f16.f16.f32 "
        "{%0,%1,%2,%3}, {%4,%5,%6,%7}, {%8,%9}, {%0,%1,%2,%3};"
        : "+f"(c[0]), "+f"(c[1]), "+f"(c[2]), "+f"(c[3])
        : "r"(a[0]), "r"(a[1]), "r"(a[2]), "r"(a[3]), "r"(b0), "r"(b1));
}
__device__ __forceinline__ void ldsm_x4(uint32_t* r, uint32_t addr) {
    asm volatile("ldmatrix.sync.aligned.m8n8.x4.shared.b16 {%0,%1,%2,%3}, [%4];"
        : "=r"(r[0]), "=r"(r[1]), "=r"(r[2]), "=r"(r[3]) : "r"(addr));
}

// ============================================================================
// fp16 mma.sync GEMM: C[M,N] = A[M,K] @ Bt[N,K]^T + bias (fp32 accum/output)
// 128x128 CTA tile, 8 warps (2x4), warp tile 64x32, K-chunk 64, double-buffer,
// ldmatrix fragment loads, hoisted addressing.
// ============================================================================
#define KCH 64
#define LDH 72                            // halves per smem row (144B)
#define GEMM_STAGE (128 * LDH)            // halves per stage per matrix
#define STAGE_B (GEMM_STAGE * 2)          // bytes per stage per matrix (18432)
#define GEMM_SMEM_BYTES (2 * STAGE_B * 2) // 73728 B

__global__ void __launch_bounds__(256, 2) gemm_f16_mma(
    const __half* __restrict__ A, const __half* __restrict__ Bt,
    const float* __restrict__ bias, float* __restrict__ C,
    int M, int N, int K)
{
    extern __shared__ __half hsm[];
    __half* As = hsm;                       // [2][128][LDH]
    __half* Bs = hsm + 2 * GEMM_STAGE;      // [2][128][LDH]

    const int tid  = threadIdx.x;
    const int wid  = tid >> 5;
    const int lane = tid & 31;
    const int wm = wid >> 2;
    const int wn = wid & 3;
    const int qr = lane >> 2;
    const int qc = lane & 3;
    const int m0 = blockIdx.y * 128;
    const int n0 = blockIdx.x * 128;
    const int lrow = lane & 15;
    const int lcol = (lane >> 4) * 8;

    // hoisted cp.async addressing: each thread owns 4 rows (row0 + 32*it), fixed c8
    const int row0 = tid >> 3;            // 0..31
    const int c8   = (tid & 7) << 3;      // 0..56
    const __half* srcA = A  + (size_t)(m0 + row0) * K + c8;
    const __half* srcB = Bt + (size_t)(n0 + row0) * K + c8;
    const uint32_t dA0 = smem_u32(As) + (uint32_t)(row0 * LDH + c8) * 2u;
    const uint32_t dB0 = smem_u32(Bs) + (uint32_t)(row0 * LDH + c8) * 2u;
    const size_t gRow = (size_t)32 * K;          // 32-row stride (halves)
    const uint32_t sRow = 32u * LDH * 2u;        // 32-row stride (bytes)

    // hoisted LDSM base addresses (stage 0, k0 = 0)
    uint32_t aAddr[4], bAddr[2];
#pragma unroll
    for (int mt = 0; mt < 4; ++mt)
        aAddr[mt] = smem_u32(As) + (uint32_t)((wm * 64 + mt * 16 + lrow) * LDH + lcol) * 2u;
#pragma unroll
    for (int nt2 = 0; nt2 < 2; ++nt2)
        bAddr[nt2] = smem_u32(Bs) + (uint32_t)((wn * 32 + nt2 * 16 + lrow) * LDH + lcol) * 2u;

    float acc[4][4][4];
#pragma unroll
    for (int i = 0; i < 4; ++i)
#pragma unroll
        for (int j = 0; j < 4; ++j)
#pragma unroll
            for (int k = 0; k < 4; ++k) acc[i][j][k] = 0.0f;

    auto load_chunk = [&](const __half* pA, const __half* pB, uint32_t sOff) {
#pragma unroll
        for (int it = 0; it < 4; ++it) {
            asm volatile("cp.async.cg.shared.global [%0], [%1], 16;"
                :: "r"(dA0 + sOff + it * sRow), "l"(pA + it * gRow) : "memory");
            asm volatile("cp.async.cg.shared.global [%0], [%1], 16;"
                :: "r"(dB0 + sOff + it * sRow), "l"(pB + it * gRow) : "memory");
        }
        asm volatile("cp.async.commit_group;" ::: "memory");
    };

    const int NCH = K / KCH;
    load_chunk(srcA, srcB, 0);
    srcA += KCH; srcB += KCH;

    for (int c = 0; c < NCH; ++c) {
        const uint32_t sOff = (c & 1) ? STAGE_B : 0u;
        if (c + 1 < NCH) {
            load_chunk(srcA, srcB, (c & 1) ? 0u : STAGE_B);
            srcA += KCH; srcB += KCH;
            asm volatile("cp.async.wait_group 1;" ::: "memory");
        } else {
            asm volatile("cp.async.wait_group 0;" ::: "memory");
        }
        __syncthreads();

#pragma unroll
        for (int ks = 0; ks < 4; ++ks) {
            const uint32_t kOff = sOff + (uint32_t)(ks * 16 * 2);
            uint32_t af[4][4];
#pragma unroll
            for (int mt = 0; mt < 4; ++mt)
                ldsm_x4(af[mt], aAddr[mt] + kOff);
            uint32_t bf[2][4];
#pragma unroll
            for (int nt2 = 0; nt2 < 2; ++nt2)
                ldsm_x4(bf[nt2], bAddr[nt2] + kOff);
#pragma unroll
            for (int mt = 0; mt < 4; ++mt)
#pragma unroll
                for (int nt = 0; nt < 4; ++nt)
                    mma_f16(acc[mt][nt], af[mt], bf[nt >> 1][nt & 1], bf[nt >> 1][2 + (nt & 1)]);
        }
        __syncthreads();
    }

#pragma unroll
    for (int mt = 0; mt < 4; ++mt) {
        const int row = m0 + wm * 64 + mt * 16 + qr;
#pragma unroll
        for (int nt = 0; nt < 4; ++nt) {
            const int col = n0 + wn * 32 + nt * 8 + 2 * qc;
            const float2 bv = *(const float2*)&bias[col];
            float2 o0, o1;
            o0.x = acc[mt][nt][0] + bv.x; o0.y = acc[mt][nt][1] + bv.y;
            o1.x = acc[mt][nt][2] + bv.x; o1.y = acc[mt][nt][3] + bv.y;
            *(float2*)&C[(size_t)row * N + col]       = o0;
            *(float2*)&C[(size_t)(row + 8) * N + col] = o1;
        }
    }
}

// ============================================================================
// float -> half bulk convert
// ============================================================================
__global__ void __launch_bounds__(256) f2h_copy(
    const float* __restrict__ src, __half* __restrict__ dst, int n4)
{
    const int i = blockIdx.x * 256 + threadIdx.x;
    if (i < n4) {
        float4 v = ((const float4*)src)[i];
        ((__half2*)dst)[2 * i]     = __floats2half2_rn(v.x, v.y);
        ((__half2*)dst)[2 * i + 1] = __floats2half2_rn(v.z, v.w);
    }
}

// ============================================================================
// Transpose + half convert: dst[Ccols][R] = h(src[R][Ccols])
// ============================================================================
__global__ void __launch_bounds__(256) transpose_h(
    const float* __restrict__ src, __half* __restrict__ dst, int R, int Ccols)
{
    __shared__ float t[32][33];
    const int tx = threadIdx.x & 31;
    const int ty = threadIdx.x >> 5;
    const int c0 = blockIdx.x * 32;
    const int r0 = blockIdx.y * 32;
#pragma unroll
    for (int j = 0; j < 4; ++j)
        t[ty + 8 * j][tx] = src[(size_t)(r0 + ty + 8 * j) * Ccols + c0 + tx];
    __syncthreads();
#pragma unroll
    for (int j = 0; j < 4; ++j)
        dst[(size_t)(c0 + ty + 8 * j) * R + r0 + tx] = __float2half_rn(t[tx][ty + 8 * j]);
}

// ============================================================================
// V transpose per head: g_v [BH, S, D] -> g_vth [BH, D, S] (half)
// ============================================================================
__global__ void __launch_bounds__(256) transpose_v_h()
{
    __shared__ float t[32][33];
    const int tx = threadIdx.x & 31;
    const int ty = threadIdx.x >> 5;
    const int d0 = blockIdx.x * 32;
    const int s0 = blockIdx.y * 32;
    const int bh = blockIdx.z;
    const float* src = g_v + (size_t)bh * SEQ * HEAD_SIZE;
    __half* dst = g_vth + (size_t)bh * HEAD_SIZE * SEQ;
#pragma unroll
    for (int j = 0; j < 4; ++j)
        t[ty + 8 * j][tx] = src[(size_t)(s0 + ty + 8 * j) * HEAD_SIZE + d0 + tx];
    __syncthreads();
#pragma unroll
    for (int j = 0; j < 4; ++j)
        dst[(size_t)(d0 + ty + 8 * j) * SEQ + s0 + tx] = __float2half_rn(t[tx][ty + 8 * j]);
}

// ============================================================================
// rotary embedding + split: Q (half, pre-scaled) / K (half) / V (fp32)
// ============================================================================
__global__ void __launch_bounds__(256) rope_split(
    const float* __restrict__ cosb, const float* __restrict__ sinb)
{
    const int t = blockIdx.x;
    const int b = t >> 10;
    const int s = t & 1023;
    const float* qkv = g_qkv + (size_t)t * QKV_N;
    const float scale = 0.08838834764831845f;   // 1/sqrt(128)

    for (int idx = threadIdx.x; idx < HIDDEN; idx += blockDim.x) {
        const int h = idx >> 7;
        const int d = idx & 127;
        const size_t src = (size_t)h * HEAD_SIZE + d;
        const size_t dst = ((size_t)(b * NUM_HEADS + h) * SEQ + s) * HEAD_SIZE + d;

        float qv = qkv[src];
        float kv = qkv[src + HIDDEN];
        float vv = qkv[src + 2 * HIDDEN];

        if (d < 2 * ROT) {
            if (d < ROT) {
                const float c  = cosb[t * ROT + d];
                const float sn = sinb[t * ROT + d];
                const float q2 = qkv[src + ROT];
                const float k2 = qkv[src + HIDDEN + ROT];
                qv = qv * c - q2 * sn;
                kv = kv * c - k2 * sn;
            } else {
                const int r = d - ROT;
                const float c  = cosb[t * ROT + r];
                const float sn = sinb[t * ROT + r];
                const float q1 = qkv[src - ROT];
                const float k1 = qkv[src + HIDDEN - ROT];
                qv = q1 * sn + qv * c;
                kv = k1 * sn + kv * c;
            }
        }
        g_qh[dst] = __float2half_rn(qv * scale);
        g_kh[dst] = __float2half_rn(kv);
        g_v[dst]  = vv;
    }
}

// ============================================================================
// flash attention v4 — fp16 mma + ldmatrix for score AND PV.
// Block 256 thr = 8 warps. Score warp tile 16x32; PV warp tile 16x64.
// ============================================================================
#define FQT 64
#define FKT 64
#define LDQ 136    // halves; 272B row stride (LDSM conflict-free)
#define LDSC 68    // floats
#define LDPH 72    // halves
#define LDVT 72    // halves

struct FlashSmem {
    __half Qs[FQT][LDQ];
    __half Ks[FKT][LDQ];
    __half Vt[HEAD_SIZE][LDVT];
    float  Sc[FQT][LDSC];
    __half Ph[FQT][LDPH];
    float m_s[FQT];
    float l_s[FQT];
    float a_s[FQT];
};

__global__ void __launch_bounds__(256) flash_f16()
{
    extern __shared__ char sraw[];
    FlashSmem& S = *reinterpret_cast<FlashSmem*>(sraw);

    const int qt = blockIdx.x;
    const int h  = blockIdx.y;
    const int b  = blockIdx.z;
    const int tid  = threadIdx.x;
    const int wid  = tid >> 5;
    const int lane = tid & 31;
    const int qr = lane >> 2;
    const int qc = lane & 3;
    const int wm = wid & 3;
    const int wn = wid >> 2;
    const int lrow = lane & 15;
    const int lcol = (lane >> 4) * 8;
    const int bh = b * NUM_HEADS + h;
    const size_t headbase = (size_t)bh * SEQ * HEAD_SIZE;

    // ---- load Q tile (half, pre-scaled): 64x128 halves = 1024 uint4 ----
    {
        const __half* qg = g_qh + headbase + (size_t)(qt * FQT) * HEAD_SIZE;
#pragma unroll
        for (int it = 0; it < 4; ++it) {
            const int flat = it * 256 + tid;
            const int r = flat >> 4;
            const int c = (flat & 15) << 3;
            *(uint4*)&S.Qs[r][c] = *(const uint4*)(qg + (size_t)r * HEAD_SIZE + c);
        }
    }
    if (tid < FQT) { S.m_s[tid] = -1e30f; S.l_s[tid] = 0.0f; }

    float oacc[8][4];
#pragma unroll
    for (int i = 0; i < 8; ++i)
#pragma unroll
        for (int j = 0; j < 4; ++j) oacc[i][j] = 0.0f;

    const int nkt = qt + 1;
    for (int kt = 0; kt < nkt; ++kt) {
        __syncthreads();
        // ---- load K tile (64x128 halves) + Vt tile (128x64 halves) ----
        {
            const __half* kg = g_kh + headbase + (size_t)(kt * FKT) * HEAD_SIZE;
#pragma unroll
            for (int it = 0; it < 4; ++it) {
                const int flat = it * 256 + tid;
                const int r = flat >> 4;
                const int c = (flat & 15) << 3;
                *(uint4*)&S.Ks[r][c] = *(const uint4*)(kg + (size_t)r * HEAD_SIZE + c);
            }
            const __half* vg = g_vth + (size_t)bh * HEAD_SIZE * SEQ + kt * FKT;
#pragma unroll
            for (int it = 0; it < 4; ++it) {
                const int flat = it * 256 + tid;
                const int d = flat >> 3;
                const int s8 = (flat & 7) << 3;
                *(uint4*)&S.Vt[d][s8] = *(const uint4*)(vg + (size_t)d * SEQ + s8);
            }
        }
        __syncthreads();

        // ---- score: S[64x64] = Qs @ Ks^T (fp16 mma, warp tile 16x32) ----
        {
            float sacc[4][4];
#pragma unroll
            for (int i = 0; i < 4; ++i)
#pragma unroll
                for (int j = 0; j < 4; ++j) sacc[i][j] = 0.0f;
            const int m0 = wm * 16;
            const int n0 = wn * 32;
            const uint32_t aBase = smem_u32(&S.Qs[m0 + lrow][lcol]);
            const uint32_t bBase0 = smem_u32(&S.Ks[n0 + lrow][lcol]);
            const uint32_t bBase1 = smem_u32(&S.Ks[n0 + 16 + lrow][lcol]);
#pragma unroll
            for (int ks = 0; ks < 8; ++ks) {
                const uint32_t kOff = (uint32_t)(ks * 16 * 2);
                uint32_t af[4], bf0[4], bf1[4];
                ldsm_x4(af, aBase + kOff);
                ldsm_x4(bf0, bBase0 + kOff);
                ldsm_x4(bf1, bBase1 + kOff);
                mma_f16(sacc[0], af, bf0[0], bf0[2]);
                mma_f16(sacc[1], af, bf0[1], bf0[3]);
                mma_f16(sacc[2], af, bf1[0], bf1[2]);
                mma_f16(sacc[3], af, bf1[1], bf1[3]);
            }
#pragma unroll
            for (int nt = 0; nt < 4; ++nt) {
                const int col = n0 + nt * 8 + 2 * qc;
                *(float2*)&S.Sc[m0 + qr    ][col] = make_float2(sacc[nt][0], sacc[nt][1]);
                *(float2*)&S.Sc[m0 + qr + 8][col] = make_float2(sacc[nt][2], sacc[nt][3]);
            }
        }
        __syncthreads();

        // ---- online softmax (4 threads per row); probs to half ----
        {
            const int row = tid >> 2;
            const int sub = tid & 3;
            const int sq  = qt * FQT + row;
            const int c0  = sub * 16;
            float sv[16];
            float mx = -1e30f;
#pragma unroll
            for (int jj = 0; jj < 16; ++jj) {
                const int cg = kt * FKT + c0 + jj;
                float s = S.Sc[row][c0 + jj];
                s = (cg > sq) ? -1e30f : s;
                sv[jj] = s;
                mx = fmaxf(mx, s);
            }
            mx = fmaxf(mx, __shfl_xor_sync(0xffffffffu, mx, 1));
            mx = fmaxf(mx, __shfl_xor_sync(0xffffffffu, mx, 2));
            const float m_old = S.m_s[row];
            const float m_new = fmaxf(m_old, mx);
            float sum = 0.0f;
#pragma unroll
            for (int jj = 0; jj < 16; jj += 2) {
                const float p0 = __expf(sv[jj]     - m_new);
                const float p1 = __expf(sv[jj + 1] - m_new);
                sum += p0 + p1;
                *(__half2*)&S.Ph[row][c0 + jj] = __floats2half2_rn(p0, p1);
            }
            sum += __shfl_xor_sync(0xffffffffu, sum, 1);
            sum += __shfl_xor_sync(0xffffffffu, sum, 2);
            __syncwarp();
            if (sub == 0) {
                const float alpha = __expf(m_old - m_new);
                S.a_s[row] = alpha;
                S.m_s[row] = m_new;
                S.l_s[row] = S.l_s[row] * alpha + sum;
            }
        }
        __syncthreads();

        // ---- PV: O += P @ Vt^T (fp16 mma, warp tile 16x64) ----
        {
            const int m0 = wm * 16;
            const int n0 = wn * 64;
            const float al0 = S.a_s[m0 + qr];
            const float al1 = S.a_s[m0 + qr + 8];
#pragma unroll
            for (int nt = 0; nt < 8; ++nt) {
                oacc[nt][0] *= al0; oacc[nt][1] *= al0;
                oacc[nt][2] *= al1; oacc[nt][3] *= al1;
            }
            const uint32_t aBase = smem_u32(&S.Ph[m0 + lrow][lcol]);
            uint32_t bBase[4];
#pragma unroll
            for (int nt2 = 0; nt2 < 4; ++nt2)
                bBase[nt2] = smem_u32(&S.Vt[n0 + nt2 * 16 + lrow][lcol]);
#pragma unroll
            for (int ks = 0; ks < 4; ++ks) {
                const uint32_t kOff = (uint32_t)(ks * 16 * 2);
                uint32_t af[4];
                ldsm_x4(af, aBase + kOff);
#pragma unroll
                for (int nt2 = 0; nt2 < 4; ++nt2) {
                    uint32_t bf[4];
                    ldsm_x4(bf, bBase[nt2] + kOff);
                    mma_f16(oacc[nt2 * 2    ], af, bf[0], bf[2]);
                    mma_f16(oacc[nt2 * 2 + 1], af, bf[1], bf[3]);
                }
            }
        }
    }

    // ---- epilogue: normalize, store as half for the fp16 dense GEMM ----
    {
        const int m0 = wm * 16;
        const int n0 = wn * 64;
        const int t0 = b * SEQ + qt * FQT;
        const float inv0 = 1.0f / S.l_s[m0 + qr];
        const float inv1 = 1.0f / S.l_s[m0 + qr + 8];
#pragma unroll
        for (int nt = 0; nt < 8; ++nt) {
            const int col = h * HEAD_SIZE + n0 + nt * 8 + 2 * qc;
            *(__half2*)&g_attnh[(size_t)(t0 + m0 + qr    ) * HIDDEN + col] =
                __floats2half2_rn(oacc[nt][0] * inv0, oacc[nt][1] * inv0);
            *(__half2*)&g_attnh[(size_t)(t0 + m0 + qr + 8) * HIDDEN + col] =
                __floats2half2_rn(oacc[nt][2] * inv1, oacc[nt][3] * inv1);
        }
    }
}

// ============================================================================
// launch
// ============================================================================
extern "C" void kernel_launch(void* const* d_in, const int* in_sizes, int n_in,
                              void* d_out, int out_size)
{
    const float* hidden  = (const float*)d_in[0];
    const float* cosb    = (const float*)d_in[1];
    const float* sinb    = (const float*)d_in[2];
    const float* W_qkv   = (const float*)d_in[3];
    const float* b_qkv   = (const float*)d_in[4];
    const float* W_dense = (const float*)d_in[5];
    const float* b_dense = (const float*)d_in[6];
    float* out = (float*)d_out;

    float *qkv_ptr;
    __half *attnh_ptr, *hidh_ptr, *wqkvTh_ptr, *wdenseTh_ptr;
    cudaGetSymbolAddress((void**)&qkv_ptr, g_qkv);
    cudaGetSymbolAddress((void**)&attnh_ptr, g_attnh);
    cudaGetSymbolAddress((void**)&hidh_ptr, g_hidh);
    cudaGetSymbolAddress((void**)&wqkvTh_ptr, g_wqkvTh);
    cudaGetSymbolAddress((void**)&wdenseTh_ptr, g_wdenseTh);

    cudaFuncSetAttribute(flash_f16, cudaFuncAttributeMaxDynamicSharedMemorySize,
                         (int)sizeof(FlashSmem));
    cudaFuncSetAttribute(gemm_f16_mma, cudaFuncAttributeMaxDynamicSharedMemorySize,
                         GEMM_SMEM_BYTES);

    // 0) operand prep (half)
    {
        const int n4 = TOTAL * HIDDEN / 4;
        f2h_copy<<<(n4 + 255) / 256, 256>>>(hidden, hidh_ptr, n4);
        transpose_h<<<dim3(QKV_N / 32, HIDDEN / 32), 256>>>(W_qkv, wqkvTh_ptr, HIDDEN, QKV_N);
        transpose_h<<<dim3(HIDDEN / 32, HIDDEN / 32), 256>>>(W_dense, wdenseTh_ptr, HIDDEN, HIDDEN);
    }
    // 1) QKV projection (fp16 mma + ldmatrix)
    gemm_f16_mma<<<dim3(QKV_N / 128, TOTAL / 128), 256, GEMM_SMEM_BYTES>>>(
        hidh_ptr, wqkvTh_ptr, b_qkv, qkv_ptr, TOTAL, QKV_N, HIDDEN);
    // 2) rotary + split (Q pre-scaled half, K half, V fp32)
    rope_split<<<TOTAL, 256>>>(cosb, sinb);
    // 2b) V transpose per head (half)
    transpose_v_h<<<dim3(HEAD_SIZE / 32, SEQ / 32, BATCH * NUM_HEADS), 256>>>();
    // 3) causal flash attention (fp16 tensor-core)
    flash_f16<<<dim3(SEQ / FQT, NUM_HEADS, BATCH), 256, sizeof(FlashSmem)>>>();
    // 4) dense projection (fp16 mma + ldmatrix)
    gemm_f16_mma<<<dim3(HIDDEN / 128, TOTAL / 128), 256, GEMM_SMEM_BYTES>>>(
        attnh_ptr, wdenseTh_ptr, b_dense, out, TOTAL, HIDDEN, HIDDEN);
}

// round 9
// speedup vs baseline: 7.0961x; 1.0101x over previous
#include <cuda_runtime.h>
#include <cuda.h>
#include <cuda_fp16.h>
#include <math.h>
#include <stdint.h>

// Problem constants
#define NUM_HEADS 16
#define HEAD_SIZE 128
#define HIDDEN    2048
#define ROT       16
#define BATCH     4
#define SEQ       1024
#define TOTAL     4096
#define QKV_N     6144

// -------- device scratch --------
__device__ __half g_qkvh[(size_t)TOTAL * QKV_N];       // QKV GEMM output (half)
__device__ __half g_qh[(size_t)TOTAL * HIDDEN];        // Q half, pre-scaled, [B,H,S,D]
__device__ __half g_kh[(size_t)TOTAL * HIDDEN];        // K half, [B,H,S,D]
__device__ float  g_v[(size_t)TOTAL * HIDDEN];         // V fp32, [B,H,S,D]
__device__ __half g_vth[(size_t)BATCH * NUM_HEADS * HEAD_SIZE * SEQ];  // V^T half [B,H,D,S]
__device__ __half g_attnh[(size_t)TOTAL * HIDDEN];     // flash output (half)
__device__ __half g_hidh[(size_t)TOTAL * HIDDEN];      // hidden states (half)
__device__ __half g_wqkvTh[(size_t)QKV_N * HIDDEN];    // W_qkv^T [N][K] half
__device__ __half g_wdenseTh[(size_t)HIDDEN * HIDDEN]; // W_dense^T [N][K] half

// ============================================================================
// helpers
// ============================================================================
__device__ __forceinline__ uint32_t smem_u32(const void* p) {
    uint32_t a;
    asm("{ .reg .u64 t; cvta.to.shared.u64 t, %1; cvt.u32.u64 %0, t; }" : "=r"(a) : "l"(p));
    return a;
}
__device__ __forceinline__ void mma_f16(float* c, const uint32_t* a, uint32_t b0, uint32_t b1) {
    asm volatile(
        "mma.sync.aligned.m16n8k16.row.col.f32.f16.f16.f32 "
        "{%0,%1,%2,%3}, {%4,%5,%6,%7}, {%8,%9}, {%0,%1,%2,%3};"
        : "+f"(c[0]), "+f"(c[1]), "+f"(c[2]), "+f"(c[3])
        : "r"(a[0]), "r"(a[1]), "r"(a[2]), "r"(a[3]), "r"(b0), "r"(b1));
}
__device__ __forceinline__ void ldsm_x4(uint32_t* r, uint32_t addr) {
    asm volatile("ldmatrix.sync.aligned.m8n8.x4.shared.b16 {%0,%1,%2,%3}, [%4];"
        : "=r"(r[0]), "=r"(r[1]), "=r"(r[2]), "=r"(r[3]) : "r"(addr));
}

// ============================================================================
// fp16 mma.sync GEMM v3: C = A[M,K] @ Bt[N,K]^T + bias
// 128x128 CTA tile, 8 warps (2x4), warp tile 64x32, K-chunk 64,
// 3-stage cp.async pipeline with a SINGLE barrier per chunk.
// HALF_OUT selects half (Ch) or fp32 (Cf) output.
// ============================================================================
#define NSTAGE 3
#define KCH 64
#define LDH 72                            // halves per smem row (144B)
#define GEMM_STAGE (128 * LDH)            // halves per stage per matrix
#define STAGE_B (GEMM_STAGE * 2)          // bytes per stage per matrix (18432)
#define GEMM_SMEM_BYTES (NSTAGE * STAGE_B * 2)   // 110592 B

template<bool HALF_OUT>
__global__ void __launch_bounds__(256, 2) gemm_f16_v3(
    const __half* __restrict__ A, const __half* __restrict__ Bt,
    const float* __restrict__ bias, float* __restrict__ Cf,
    __half* __restrict__ Ch, int M, int N, int K)
{
    extern __shared__ __half hsm[];
    __half* As = hsm;                           // [NSTAGE][128][LDH]
    __half* Bs = hsm + NSTAGE * GEMM_STAGE;     // [NSTAGE][128][LDH]

    const int tid  = threadIdx.x;
    const int wid  = tid >> 5;
    const int lane = tid & 31;
    const int wm = wid >> 2;
    const int wn = wid & 3;
    const int qr = lane >> 2;
    const int qc = lane & 3;
    const int m0 = blockIdx.y * 128;
    const int n0 = blockIdx.x * 128;
    const int lrow = lane & 15;
    const int lcol = (lane >> 4) * 8;

    // hoisted cp.async addressing
    const int row0 = tid >> 3;            // 0..31
    const int c8   = (tid & 7) << 3;      // 0..56
    const __half* srcA = A  + (size_t)(m0 + row0) * K + c8;
    const __half* srcB = Bt + (size_t)(n0 + row0) * K + c8;
    const uint32_t dA0 = smem_u32(As) + (uint32_t)(row0 * LDH + c8) * 2u;
    const uint32_t dB0 = smem_u32(Bs) + (uint32_t)(row0 * LDH + c8) * 2u;
    const size_t gRow = (size_t)32 * K;
    const uint32_t sRow = 32u * LDH * 2u;

    // hoisted LDSM base addresses (stage 0, k0 = 0)
    uint32_t aAddr[4], bAddr[2];
#pragma unroll
    for (int mt = 0; mt < 4; ++mt)
        aAddr[mt] = smem_u32(As) + (uint32_t)((wm * 64 + mt * 16 + lrow) * LDH + lcol) * 2u;
#pragma unroll
    for (int nt2 = 0; nt2 < 2; ++nt2)
        bAddr[nt2] = smem_u32(Bs) + (uint32_t)((wn * 32 + nt2 * 16 + lrow) * LDH + lcol) * 2u;

    float acc[4][4][4];
#pragma unroll
    for (int i = 0; i < 4; ++i)
#pragma unroll
        for (int j = 0; j < 4; ++j)
#pragma unroll
            for (int k = 0; k < 4; ++k) acc[i][j][k] = 0.0f;

    auto load_chunk = [&](const __half* pA, const __half* pB, uint32_t sOff) {
#pragma unroll
        for (int it = 0; it < 4; ++it) {
            asm volatile("cp.async.cg.shared.global [%0], [%1], 16;"
                :: "r"(dA0 + sOff + it * sRow), "l"(pA + it * gRow) : "memory");
            asm volatile("cp.async.cg.shared.global [%0], [%1], 16;"
                :: "r"(dB0 + sOff + it * sRow), "l"(pB + it * gRow) : "memory");
        }
        asm volatile("cp.async.commit_group;" ::: "memory");
    };

    const int NCH = K / KCH;
    // prologue: chunks 0 and 1 into stages 0,1
    load_chunk(srcA, srcB, 0);
    srcA += KCH; srcB += KCH;
    load_chunk(srcA, srcB, STAGE_B);
    srcA += KCH; srcB += KCH;

    uint32_t sC = 0;                    // compute-stage byte offset
    uint32_t sL = 2 * STAGE_B;          // next load-stage byte offset

    for (int c = 0; c < NCH; ++c) {
        if (c + 1 < NCH) { asm volatile("cp.async.wait_group 1;" ::: "memory"); }
        else             { asm volatile("cp.async.wait_group 0;" ::: "memory"); }
        __syncthreads();   // single barrier per chunk: protects stage sL reuse

        if (c + 2 < NCH) {
            load_chunk(srcA, srcB, sL);
            srcA += KCH; srcB += KCH;
            sL += STAGE_B; if (sL == NSTAGE * STAGE_B) sL = 0;
        }

#pragma unroll
        for (int ks = 0; ks < 4; ++ks) {
            const uint32_t kOff = sC + (uint32_t)(ks * 16 * 2);
            uint32_t af[4][4];
#pragma unroll
            for (int mt = 0; mt < 4; ++mt)
                ldsm_x4(af[mt], aAddr[mt] + kOff);
            uint32_t bf[2][4];
#pragma unroll
            for (int nt2 = 0; nt2 < 2; ++nt2)
                ldsm_x4(bf[nt2], bAddr[nt2] + kOff);
#pragma unroll
            for (int mt = 0; mt < 4; ++mt)
#pragma unroll
                for (int nt = 0; nt < 4; ++nt)
                    mma_f16(acc[mt][nt], af[mt], bf[nt >> 1][nt & 1], bf[nt >> 1][2 + (nt & 1)]);
        }
        sC += STAGE_B; if (sC == NSTAGE * STAGE_B) sC = 0;
    }

#pragma unroll
    for (int mt = 0; mt < 4; ++mt) {
        const int row = m0 + wm * 64 + mt * 16 + qr;
#pragma unroll
        for (int nt = 0; nt < 4; ++nt) {
            const int col = n0 + wn * 32 + nt * 8 + 2 * qc;
            const float2 bv = *(const float2*)&bias[col];
            const float v00 = acc[mt][nt][0] + bv.x, v01 = acc[mt][nt][1] + bv.y;
            const float v10 = acc[mt][nt][2] + bv.x, v11 = acc[mt][nt][3] + bv.y;
            if (HALF_OUT) {
                *(__half2*)&Ch[(size_t)row * N + col]       = __floats2half2_rn(v00, v01);
                *(__half2*)&Ch[(size_t)(row + 8) * N + col] = __floats2half2_rn(v10, v11);
            } else {
                *(float2*)&Cf[(size_t)row * N + col]       = make_float2(v00, v01);
                *(float2*)&Cf[(size_t)(row + 8) * N + col] = make_float2(v10, v11);
            }
        }
    }
}

// ============================================================================
// float -> half bulk convert
// ============================================================================
__global__ void __launch_bounds__(256) f2h_copy(
    const float* __restrict__ src, __half* __restrict__ dst, int n4)
{
    const int i = blockIdx.x * 256 + threadIdx.x;
    if (i < n4) {
        float4 v = ((const float4*)src)[i];
        ((__half2*)dst)[2 * i]     = __floats2half2_rn(v.x, v.y);
        ((__half2*)dst)[2 * i + 1] = __floats2half2_rn(v.z, v.w);
    }
}

// ============================================================================
// Transpose + half convert: dst[Ccols][R] = h(src[R][Ccols])
// ============================================================================
__global__ void __launch_bounds__(256) transpose_h(
    const float* __restrict__ src, __half* __restrict__ dst, int R, int Ccols)
{
    __shared__ float t[32][33];
    const int tx = threadIdx.x & 31;
    const int ty = threadIdx.x >> 5;
    const int c0 = blockIdx.x * 32;
    const int r0 = blockIdx.y * 32;
#pragma unroll
    for (int j = 0; j < 4; ++j)
        t[ty + 8 * j][tx] = src[(size_t)(r0 + ty + 8 * j) * Ccols + c0 + tx];
    __syncthreads();
#pragma unroll
    for (int j = 0; j < 4; ++j)
        dst[(size_t)(c0 + ty + 8 * j) * R + r0 + tx] = __float2half_rn(t[tx][ty + 8 * j]);
}

// ============================================================================
// V transpose per head: g_v [BH, S, D] -> g_vth [BH, D, S] (half)
// ============================================================================
__global__ void __launch_bounds__(256) transpose_v_h()
{
    __shared__ float t[32][33];
    const int tx = threadIdx.x & 31;
    const int ty = threadIdx.x >> 5;
    const int d0 = blockIdx.x * 32;
    const int s0 = blockIdx.y * 32;
    const int bh = blockIdx.z;
    const float* src = g_v + (size_t)bh * SEQ * HEAD_SIZE;
    __half* dst = g_vth + (size_t)bh * HEAD_SIZE * SEQ;
#pragma unroll
    for (int j = 0; j < 4; ++j)
        t[ty + 8 * j][tx] = src[(size_t)(s0 + ty + 8 * j) * HEAD_SIZE + d0 + tx];
    __syncthreads();
#pragma unroll
    for (int j = 0; j < 4; ++j)
        dst[(size_t)(d0 + ty + 8 * j) * SEQ + s0 + tx] = __float2half_rn(t[tx][ty + 8 * j]);
}

// ============================================================================
// rotary embedding + split (reads half QKV): Q (half, pre-scaled) / K / V(f32)
// ============================================================================
__global__ void __launch_bounds__(256) rope_split(
    const float* __restrict__ cosb, const float* __restrict__ sinb)
{
    const int t = blockIdx.x;
    const int b = t >> 10;
    const int s = t & 1023;
    const __half* qkv = g_qkvh + (size_t)t * QKV_N;
    const float scale = 0.08838834764831845f;   // 1/sqrt(128)

    for (int idx = threadIdx.x; idx < HIDDEN; idx += blockDim.x) {
        const int h = idx >> 7;
        const int d = idx & 127;
        const size_t src = (size_t)h * HEAD_SIZE + d;
        const size_t dst = ((size_t)(b * NUM_HEADS + h) * SEQ + s) * HEAD_SIZE + d;

        float qv = __half2float(qkv[src]);
        float kv = __half2float(qkv[src + HIDDEN]);
        float vv = __half2float(qkv[src + 2 * HIDDEN]);

        if (d < 2 * ROT) {
            if (d < ROT) {
                const float c  = cosb[t * ROT + d];
                const float sn = sinb[t * ROT + d];
                const float q2 = __half2float(qkv[src + ROT]);
                const float k2 = __half2float(qkv[src + HIDDEN + ROT]);
                qv = qv * c - q2 * sn;
                kv = kv * c - k2 * sn;
            } else {
                const int r = d - ROT;
                const float c  = cosb[t * ROT + r];
                const float sn = sinb[t * ROT + r];
                const float q1 = __half2float(qkv[src - ROT]);
                const float k1 = __half2float(qkv[src + HIDDEN - ROT]);
                qv = q1 * sn + qv * c;
                kv = k1 * sn + kv * c;
            }
        }
        g_qh[dst] = __float2half_rn(qv * scale);
        g_kh[dst] = __float2half_rn(kv);
        g_v[dst]  = vv;
    }
}

// ============================================================================
// flash attention v4 — fp16 mma + ldmatrix for score AND PV. (unchanged)
// ============================================================================
#define FQT 64
#define FKT 64
#define LDQ 136
#define LDSC 68
#define LDPH 72
#define LDVT 72

struct FlashSmem {
    __half Qs[FQT][LDQ];
    __half Ks[FKT][LDQ];
    __half Vt[HEAD_SIZE][LDVT];
    float  Sc[FQT][LDSC];
    __half Ph[FQT][LDPH];
    float m_s[FQT];
    float l_s[FQT];
    float a_s[FQT];
};

__global__ void __launch_bounds__(256) flash_f16()
{
    extern __shared__ char sraw[];
    FlashSmem& S = *reinterpret_cast<FlashSmem*>(sraw);

    const int qt = blockIdx.x;
    const int h  = blockIdx.y;
    const int b  = blockIdx.z;
    const int tid  = threadIdx.x;
    const int wid  = tid >> 5;
    const int lane = tid & 31;
    const int qr = lane >> 2;
    const int qc = lane & 3;
    const int wm = wid & 3;
    const int wn = wid >> 2;
    const int lrow = lane & 15;
    const int lcol = (lane >> 4) * 8;
    const int bh = b * NUM_HEADS + h;
    const size_t headbase = (size_t)bh * SEQ * HEAD_SIZE;

    {
        const __half* qg = g_qh + headbase + (size_t)(qt * FQT) * HEAD_SIZE;
#pragma unroll
        for (int it = 0; it < 4; ++it) {
            const int flat = it * 256 + tid;
            const int r = flat >> 4;
            const int c = (flat & 15) << 3;
            *(uint4*)&S.Qs[r][c] = *(const uint4*)(qg + (size_t)r * HEAD_SIZE + c);
        }
    }
    if (tid < FQT) { S.m_s[tid] = -1e30f; S.l_s[tid] = 0.0f; }

    float oacc[8][4];
#pragma unroll
    for (int i = 0; i < 8; ++i)
#pragma unroll
        for (int j = 0; j < 4; ++j) oacc[i][j] = 0.0f;

    const int nkt = qt + 1;
    for (int kt = 0; kt < nkt; ++kt) {
        __syncthreads();
        {
            const __half* kg = g_kh + headbase + (size_t)(kt * FKT) * HEAD_SIZE;
#pragma unroll
            for (int it = 0; it < 4; ++it) {
                const int flat = it * 256 + tid;
                const int r = flat >> 4;
                const int c = (flat & 15) << 3;
                *(uint4*)&S.Ks[r][c] = *(const uint4*)(kg + (size_t)r * HEAD_SIZE + c);
            }
            const __half* vg = g_vth + (size_t)bh * HEAD_SIZE * SEQ + kt * FKT;
#pragma unroll
            for (int it = 0; it < 4; ++it) {
                const int flat = it * 256 + tid;
                const int d = flat >> 3;
                const int s8 = (flat & 7) << 3;
                *(uint4*)&S.Vt[d][s8] = *(const uint4*)(vg + (size_t)d * SEQ + s8);
            }
        }
        __syncthreads();

        // score
        {
            float sacc[4][4];
#pragma unroll
            for (int i = 0; i < 4; ++i)
#pragma unroll
                for (int j = 0; j < 4; ++j) sacc[i][j] = 0.0f;
            const int m0 = wm * 16;
            const int n0 = wn * 32;
            const uint32_t aBase = smem_u32(&S.Qs[m0 + lrow][lcol]);
            const uint32_t bBase0 = smem_u32(&S.Ks[n0 + lrow][lcol]);
            const uint32_t bBase1 = smem_u32(&S.Ks[n0 + 16 + lrow][lcol]);
#pragma unroll
            for (int ks = 0; ks < 8; ++ks) {
                const uint32_t kOff = (uint32_t)(ks * 16 * 2);
                uint32_t af[4], bf0[4], bf1[4];
                ldsm_x4(af, aBase + kOff);
                ldsm_x4(bf0, bBase0 + kOff);
                ldsm_x4(bf1, bBase1 + kOff);
                mma_f16(sacc[0], af, bf0[0], bf0[2]);
                mma_f16(sacc[1], af, bf0[1], bf0[3]);
                mma_f16(sacc[2], af, bf1[0], bf1[2]);
                mma_f16(sacc[3], af, bf1[1], bf1[3]);
            }
#pragma unroll
            for (int nt = 0; nt < 4; ++nt) {
                const int col = n0 + nt * 8 + 2 * qc;
                *(float2*)&S.Sc[m0 + qr    ][col] = make_float2(sacc[nt][0], sacc[nt][1]);
                *(float2*)&S.Sc[m0 + qr + 8][col] = make_float2(sacc[nt][2], sacc[nt][3]);
            }
        }
        __syncthreads();

        // online softmax
        {
            const int row = tid >> 2;
            const int sub = tid & 3;
            const int sq  = qt * FQT + row;
            const int c0  = sub * 16;
            float sv[16];
            float mx = -1e30f;
#pragma unroll
            for (int jj = 0; jj < 16; ++jj) {
                const int cg = kt * FKT + c0 + jj;
                float s = S.Sc[row][c0 + jj];
                s = (cg > sq) ? -1e30f : s;
                sv[jj] = s;
                mx = fmaxf(mx, s);
            }
            mx = fmaxf(mx, __shfl_xor_sync(0xffffffffu, mx, 1));
            mx = fmaxf(mx, __shfl_xor_sync(0xffffffffu, mx, 2));
            const float m_old = S.m_s[row];
            const float m_new = fmaxf(m_old, mx);
            float sum = 0.0f;
#pragma unroll
            for (int jj = 0; jj < 16; jj += 2) {
                const float p0 = __expf(sv[jj]     - m_new);
                const float p1 = __expf(sv[jj + 1] - m_new);
                sum += p0 + p1;
                *(__half2*)&S.Ph[row][c0 + jj] = __floats2half2_rn(p0, p1);
            }
            sum += __shfl_xor_sync(0xffffffffu, sum, 1);
            sum += __shfl_xor_sync(0xffffffffu, sum, 2);
            __syncwarp();
            if (sub == 0) {
                const float alpha = __expf(m_old - m_new);
                S.a_s[row] = alpha;
                S.m_s[row] = m_new;
                S.l_s[row] = S.l_s[row] * alpha + sum;
            }
        }
        __syncthreads();

        // PV
        {
            const int m0 = wm * 16;
            const int n0 = wn * 64;
            const float al0 = S.a_s[m0 + qr];
            const float al1 = S.a_s[m0 + qr + 8];
#pragma unroll
            for (int nt = 0; nt < 8; ++nt) {
                oacc[nt][0] *= al0; oacc[nt][1] *= al0;
                oacc[nt][2] *= al1; oacc[nt][3] *= al1;
            }
            const uint32_t aBase = smem_u32(&S.Ph[m0 + lrow][lcol]);
            uint32_t bBase[4];
#pragma unroll
            for (int nt2 = 0; nt2 < 4; ++nt2)
                bBase[nt2] = smem_u32(&S.Vt[n0 + nt2 * 16 + lrow][lcol]);
#pragma unroll
            for (int ks = 0; ks < 4; ++ks) {
                const uint32_t kOff = (uint32_t)(ks * 16 * 2);
                uint32_t af[4];
                ldsm_x4(af, aBase + kOff);
#pragma unroll
                for (int nt2 = 0; nt2 < 4; ++nt2) {
                    uint32_t bf[4];
                    ldsm_x4(bf, bBase[nt2] + kOff);
                    mma_f16(oacc[nt2 * 2    ], af, bf[0], bf[2]);
                    mma_f16(oacc[nt2 * 2 + 1], af, bf[1], bf[3]);
                }
            }
        }
    }

    // epilogue
    {
        const int m0 = wm * 16;
        const int n0 = wn * 64;
        const int t0 = b * SEQ + qt * FQT;
        const float inv0 = 1.0f / S.l_s[m0 + qr];
        const float inv1 = 1.0f / S.l_s[m0 + qr + 8];
#pragma unroll
        for (int nt = 0; nt < 8; ++nt) {
            const int col = h * HEAD_SIZE + n0 + nt * 8 + 2 * qc;
            *(__half2*)&g_attnh[(size_t)(t0 + m0 + qr    ) * HIDDEN + col] =
                __floats2half2_rn(oacc[nt][0] * inv0, oacc[nt][1] * inv0);
            *(__half2*)&g_attnh[(size_t)(t0 + m0 + qr + 8) * HIDDEN + col] =
                __floats2half2_rn(oacc[nt][2] * inv1, oacc[nt][3] * inv1);
        }
    }
}

// ============================================================================
// launch
// ============================================================================
extern "C" void kernel_launch(void* const* d_in, const int* in_sizes, int n_in,
                              void* d_out, int out_size)
{
    const float* hidden  = (const float*)d_in[0];
    const float* cosb    = (const float*)d_in[1];
    const float* sinb    = (const float*)d_in[2];
    const float* W_qkv   = (const float*)d_in[3];
    const float* b_qkv   = (const float*)d_in[4];
    const float* W_dense = (const float*)d_in[5];
    const float* b_dense = (const float*)d_in[6];
    float* out = (float*)d_out;

    __half *qkvh_ptr, *attnh_ptr, *hidh_ptr, *wqkvTh_ptr, *wdenseTh_ptr;
    cudaGetSymbolAddress((void**)&qkvh_ptr, g_qkvh);
    cudaGetSymbolAddress((void**)&attnh_ptr, g_attnh);
    cudaGetSymbolAddress((void**)&hidh_ptr, g_hidh);
    cudaGetSymbolAddress((void**)&wqkvTh_ptr, g_wqkvTh);
    cudaGetSymbolAddress((void**)&wdenseTh_ptr, g_wdenseTh);

    cudaFuncSetAttribute(flash_f16, cudaFuncAttributeMaxDynamicSharedMemorySize,
                         (int)sizeof(FlashSmem));
    cudaFuncSetAttribute(gemm_f16_v3<true>,  cudaFuncAttributeMaxDynamicSharedMemorySize,
                         GEMM_SMEM_BYTES);
    cudaFuncSetAttribute(gemm_f16_v3<false>, cudaFuncAttributeMaxDynamicSharedMemorySize,
                         GEMM_SMEM_BYTES);

    // 0) operand prep (half)
    {
        const int n4 = TOTAL * HIDDEN / 4;
        f2h_copy<<<(n4 + 255) / 256, 256>>>(hidden, hidh_ptr, n4);
        transpose_h<<<dim3(QKV_N / 32, HIDDEN / 32), 256>>>(W_qkv, wqkvTh_ptr, HIDDEN, QKV_N);
        transpose_h<<<dim3(HIDDEN / 32, HIDDEN / 32), 256>>>(W_dense, wdenseTh_ptr, HIDDEN, HIDDEN);
    }
    // 1) QKV projection (fp16 mma, 3-stage, half output)
    gemm_f16_v3<true><<<dim3(QKV_N / 128, TOTAL / 128), 256, GEMM_SMEM_BYTES>>>(
        hidh_ptr, wqkvTh_ptr, b_qkv, nullptr, qkvh_ptr, TOTAL, QKV_N, HIDDEN);
    // 2) rotary + split
    rope_split<<<TOTAL, 256>>>(cosb, sinb);
    // 2b) V transpose per head (half)
    transpose_v_h<<<dim3(HEAD_SIZE / 32, SEQ / 32, BATCH * NUM_HEADS), 256>>>();
    // 3) causal flash attention (fp16 tensor-core)
    flash_f16<<<dim3(SEQ / FQT, NUM_HEADS, BATCH), 256, sizeof(FlashSmem)>>>();
    // 4) dense projection (fp16 mma, 3-stage, fp32 output)
    gemm_f16_v3<false><<<dim3(HIDDEN / 128, TOTAL / 128), 256, GEMM_SMEM_BYTES>>>(
        attnh_ptr, wdenseTh_ptr, b_dense, out, nullptr, TOTAL, HIDDEN, HIDDEN);
}